// round 5
// baseline (speedup 1.0000x reference)
#include <cuda_runtime.h>
#include <math.h>

#define B 32
#define C 128
#define NN 4096
#define HEADS 4
#define DH 32
#define HIDDEN 128
#define QSCALE 0.17677669529663687f   /* 32^-0.5 */
#define GEPS 1e-5f

// ---------------- scratch ----------------
__device__ float g_qkv[(size_t)B * 384 * NN];  // 0-127 q (softmaxed), 128-255 k, 256-383 v
__device__ float g_ctx[B * HEADS * DH * DH];   // unnormalized ctx partials
__device__ float g_rsum[B * HIDDEN];           // per (b, row) sum of exp(k)
__device__ float g_M[B * HIDDEN * HIDDEN];
__device__ float g_y[(size_t)B * C * NN];
__device__ float g_sum[B];
__device__ float g_sumsq[B];

__device__ __forceinline__ float cvt_tf32(float x) {
    asm("cvt.rna.tf32.f32 %0, %0;" : "+f"(x));
    return x;
}

__device__ __forceinline__ void mma_tf32(float* d, const float* a, const float* b) {
    asm("mma.sync.aligned.m16n8k8.row.col.f32.tf32.tf32.f32 "
        "{%0,%1,%2,%3}, {%4,%5,%6,%7}, {%8,%9}, {%0,%1,%2,%3};"
        : "+f"(d[0]), "+f"(d[1]), "+f"(d[2]), "+f"(d[3])
        : "f"(a[0]), "f"(a[1]), "f"(a[2]), "f"(a[3]), "f"(b[0]), "f"(b[1]));
}

// ---------------- K0: zero accumulators ----------------
__global__ void __launch_bounds__(256) k0_zero() {
    int gid = blockIdx.x * 256 + threadIdx.x;
    float4 z = make_float4(0.f, 0.f, 0.f, 0.f);
    if (gid < 32768) ((float4*)g_ctx)[gid] = z;
    if (gid < 1024)  ((float4*)g_rsum)[gid] = z;
    if (gid < 32) { g_sum[gid] = 0.f; g_sumsq[gid] = 0.f; }
}

// ---------------- shared mainloop helpers (double-buffered tf32 GEMM) ------
// block tile 128x128, K=128, slabs of 16; smem stage = [16][132]
#define SLAB 2112   /* 16*132 */

struct Frag { float d[4][4][4]; };

__device__ __forceinline__ void stage_store(
    float* sA, float* sB, int arow, int ah, int bk, int bn,
    const float4& w0, const float4& w1, const float4& x0, const float4& x1)
{
    sA[(ah * 8 + 0) * 132 + arow] = cvt_tf32(w0.x);
    sA[(ah * 8 + 1) * 132 + arow] = cvt_tf32(w0.y);
    sA[(ah * 8 + 2) * 132 + arow] = cvt_tf32(w0.z);
    sA[(ah * 8 + 3) * 132 + arow] = cvt_tf32(w0.w);
    sA[(ah * 8 + 4) * 132 + arow] = cvt_tf32(w1.x);
    sA[(ah * 8 + 5) * 132 + arow] = cvt_tf32(w1.y);
    sA[(ah * 8 + 6) * 132 + arow] = cvt_tf32(w1.z);
    sA[(ah * 8 + 7) * 132 + arow] = cvt_tf32(w1.w);
    float* bp = &sB[bk * 132 + bn];
    bp[0] = cvt_tf32(x0.x); bp[1] = cvt_tf32(x0.y);
    bp[2] = cvt_tf32(x0.z); bp[3] = cvt_tf32(x0.w);
    bp[4] = cvt_tf32(x1.x); bp[5] = cvt_tf32(x1.y);
    bp[6] = cvt_tf32(x1.z); bp[7] = cvt_tf32(x1.w);
}

__device__ __forceinline__ void slab_mma(
    Frag& f, const float* sA, const float* sB,
    int mbase, int nbase, int gid, int tig)
{
#pragma unroll
    for (int ks = 0; ks < 16; ks += 8) {
        float a[4][4], bf[4][2];
#pragma unroll
        for (int mt = 0; mt < 4; mt++) {
            int row = mbase + mt * 16 + gid;
            a[mt][0] = sA[(ks + tig) * 132 + row];
            a[mt][1] = sA[(ks + tig) * 132 + row + 8];
            a[mt][2] = sA[(ks + tig + 4) * 132 + row];
            a[mt][3] = sA[(ks + tig + 4) * 132 + row + 8];
        }
#pragma unroll
        for (int nt = 0; nt < 4; nt++) {
            int col = nbase + nt * 8 + gid;
            bf[nt][0] = sB[(ks + tig) * 132 + col];
            bf[nt][1] = sB[(ks + tig + 4) * 132 + col];
        }
#pragma unroll
        for (int mt = 0; mt < 4; mt++)
#pragma unroll
            for (int nt = 0; nt < 4; nt++)
                mma_tf32(f.d[mt][nt], a[mt], bf[nt]);
    }
}

// ---------------- K1: tf32 mma qkv projection + fused q softmax ----------------
// grid (32 ncol, 3 rowtile, 32 b), 256 threads (8 warps, 2x4)
__global__ void __launch_bounds__(256) k1_proj(
    const float* __restrict__ x,
    const float* __restrict__ Wq,
    const float* __restrict__ Wk,
    const float* __restrict__ Wv)
{
    extern __shared__ float smem[];
    float* sA = smem;                 // [2][16][132]
    float* sB = smem + 2 * SLAB;      // [2][16][132]
    float* stage = smem;              // reused [128][132] for q epilogue

    const int b  = blockIdx.z;
    const int rowtile = blockIdx.y;
    const int n0 = blockIdx.x * 128;
    const int tid = threadIdx.x;
    const int lane = tid & 31, wid = tid >> 5;
    const int mbase = (wid >> 2) * 64, nbase = (wid & 3) * 32;
    const int gid = lane >> 2, tig = lane & 3;

    const float* Wp = (rowtile == 0) ? Wq : ((rowtile == 1) ? Wk : Wv);
    const float* xb = x + (size_t)b * C * NN + n0;

    const int arow = tid & 127, ah = tid >> 7;
    const int bk = tid >> 4, bn = (tid & 15) * 8;

    Frag f;
#pragma unroll
    for (int mt = 0; mt < 4; mt++)
#pragma unroll
        for (int nt = 0; nt < 4; nt++)
#pragma unroll
            for (int r = 0; r < 4; r++) f.d[mt][nt][r] = 0.f;

    // preload slab 0
    float4 w0 = *(const float4*)&Wp[arow * 128 + ah * 8];
    float4 w1 = *(const float4*)&Wp[arow * 128 + ah * 8 + 4];
    float4 x0 = *(const float4*)&xb[(size_t)bk * NN + bn];
    float4 x1 = *(const float4*)&xb[(size_t)bk * NN + bn + 4];
    stage_store(sA, sB, arow, ah, bk, bn, w0, w1, x0, x1);
    __syncthreads();

    for (int kt = 0; kt < 8; kt++) {
        const int cur = kt & 1;
        if (kt < 7) {
            const int k0 = (kt + 1) * 16;
            w0 = *(const float4*)&Wp[arow * 128 + k0 + ah * 8];
            w1 = *(const float4*)&Wp[arow * 128 + k0 + ah * 8 + 4];
            x0 = *(const float4*)&xb[(size_t)(k0 + bk) * NN + bn];
            x1 = *(const float4*)&xb[(size_t)(k0 + bk) * NN + bn + 4];
        }
        slab_mma(f, sA + cur * SLAB, sB + cur * SLAB, mbase, nbase, gid, tig);
        if (kt < 7) {
            stage_store(sA + (1 - cur) * SLAB, sB + (1 - cur) * SLAB,
                        arow, ah, bk, bn, w0, w1, x0, x1);
            __syncthreads();
        }
    }

    if (rowtile != 0) {
        float* outp = g_qkv + ((size_t)b * 384 + rowtile * 128) * NN + n0;
#pragma unroll
        for (int mt = 0; mt < 4; mt++) {
#pragma unroll
            for (int nt = 0; nt < 4; nt++) {
                int row = mbase + mt * 16 + gid;
                int col = nbase + nt * 8 + tig * 2;
                *(float2*)&outp[(size_t)row * NN + col] =
                    make_float2(f.d[mt][nt][0], f.d[mt][nt][1]);
                *(float2*)&outp[(size_t)(row + 8) * NN + col] =
                    make_float2(f.d[mt][nt][2], f.d[mt][nt][3]);
            }
        }
        return;
    }

    // q: stage -> softmax over d per (h, col) -> coalesced global write
    __syncthreads();
#pragma unroll
    for (int mt = 0; mt < 4; mt++) {
#pragma unroll
        for (int nt = 0; nt < 4; nt++) {
            int row = mbase + mt * 16 + gid;
            int col = nbase + nt * 8 + tig * 2;
            *(float2*)&stage[row * 132 + col] = make_float2(f.d[mt][nt][0], f.d[mt][nt][1]);
            *(float2*)&stage[(row + 8) * 132 + col] = make_float2(f.d[mt][nt][2], f.d[mt][nt][3]);
        }
    }
    __syncthreads();

    float* outq = g_qkv + (size_t)b * 384 * NN + n0;
#pragma unroll
    for (int t = tid; t < 512; t += 256) {
        const int col = t & 127;
        const int h = t >> 7;
        float sum = 0.f;
#pragma unroll
        for (int dd = 0; dd < 32; dd++) {
            float* p = &stage[(h * 32 + dd) * 132 + col];
            float e = __expf(*p);
            *p = e;
            sum += e;
        }
        float inv = QSCALE / sum;
#pragma unroll
        for (int dd = 0; dd < 32; dd++)
            outq[(size_t)(h * 32 + dd) * NN + col] = stage[(h * 32 + dd) * 132 + col] * inv;
    }
}

// ---------------- K2: partial ctx = exp(k) @ v^T + partial rowsum ----------------
__global__ void __launch_bounds__(256) k2_ctx()
{
    const int bh = blockIdx.y;
    const int b = bh >> 2, h = bh & 3;
    const int cbase = blockIdx.x * 512;
    const float* kb = g_qkv + ((size_t)b * 384 + 128 + h * 32) * NN + cbase;
    const float* vb = g_qkv + ((size_t)b * 384 + 256 + h * 32) * NN + cbase;

    __shared__ float sK[32 * 128];
    __shared__ float sVT[128 * 36];

    const int tid = threadIdx.x;
    const int d  = tid >> 3;
    const int e0 = (tid & 7) * 4;
    const int ld_row = tid >> 3;
    const int ld_c   = (tid & 7) * 16;

    float4 acc = make_float4(0.f, 0.f, 0.f, 0.f);
    float lsum = 0.f;

    for (int c0 = 0; c0 < 512; c0 += 128) {
        __syncthreads();
        {
            const float* kr = kb + (size_t)ld_row * NN + c0 + ld_c;
#pragma unroll
            for (int q4 = 0; q4 < 4; q4++) {
                float4 t = *(const float4*)(kr + q4 * 4);
                float e0v = __expf(t.x), e1v = __expf(t.y);
                float e2v = __expf(t.z), e3v = __expf(t.w);
                int base = ld_row * 128 + ld_c + q4 * 4;
                sK[base + 0] = e0v; sK[base + 1] = e1v;
                sK[base + 2] = e2v; sK[base + 3] = e3v;
                lsum += e0v + e1v + e2v + e3v;
            }
            const float* vr = vb + (size_t)ld_row * NN + c0 + ld_c;
#pragma unroll
            for (int q4 = 0; q4 < 4; q4++) {
                float4 t = *(const float4*)(vr + q4 * 4);
                int nc = ld_c + q4 * 4;
                sVT[(nc + 0) * 36 + ld_row] = t.x;
                sVT[(nc + 1) * 36 + ld_row] = t.y;
                sVT[(nc + 2) * 36 + ld_row] = t.z;
                sVT[(nc + 3) * 36 + ld_row] = t.w;
            }
        }
        __syncthreads();
#pragma unroll 4
        for (int n = 0; n < 128; n++) {
            float kd = sK[d * 128 + n];
            float4 vv = *(const float4*)&sVT[n * 36 + e0];
            acc.x += kd * vv.x; acc.y += kd * vv.y;
            acc.z += kd * vv.z; acc.w += kd * vv.w;
        }
    }

#pragma unroll
    for (int o = 4; o; o >>= 1) lsum += __shfl_xor_sync(0xffffffffu, lsum, o);
    if ((tid & 7) == 0)
        atomicAdd(&g_rsum[b * HIDDEN + h * 32 + ld_row], lsum);

    float* cp = &g_ctx[((size_t)bh * 32 + d) * 32 + e0];
    atomicAdd(cp + 0, acc.x);
    atomicAdd(cp + 1, acc.y);
    atomicAdd(cp + 2, acc.z);
    atomicAdd(cp + 3, acc.w);
}

// ---------------- K3: M_b = Wo @ blockdiag(ctx^T / rsum) ----------------
// grid (32, 32): 4 o-rows per block, 2 cols per thread -> 1024 blocks
__global__ void __launch_bounds__(256) k3_fold(const float* __restrict__ Wo)
{
    const int b = blockIdx.y;
    const int og = blockIdx.x * 4;
    __shared__ float sctx[HEADS * DH * DH];
    __shared__ float sinv[HIDDEN];
    const int tid = threadIdx.x;
#pragma unroll
    for (int rr = 0; rr < 4; rr++) {
        int idx = tid + rr * 256;
        *(float4*)&sctx[idx * 4] = *(const float4*)&g_ctx[(size_t)b * 4096 + idx * 4];
    }
    if (tid < 128) sinv[tid] = 1.0f / g_rsum[b * HIDDEN + tid];
    __syncthreads();

    const int o = og + (tid >> 6);
    const int col0 = (tid & 63) * 2;
    const int h = col0 >> 5;
    const int d0 = col0 & 31;

    float wo[32];
#pragma unroll
    for (int q4 = 0; q4 < 8; q4++) {
        float4 t = *(const float4*)&Wo[o * 128 + h * 32 + q4 * 4];
        wo[q4 * 4 + 0] = t.x; wo[q4 * 4 + 1] = t.y;
        wo[q4 * 4 + 2] = t.z; wo[q4 * 4 + 3] = t.w;
    }
    float s0 = 0.f, s1 = 0.f;
#pragma unroll
    for (int q4 = 0; q4 < 8; q4++) {
        float4 c0v = *(const float4*)&sctx[(h * 32 + d0) * 32 + q4 * 4];
        float4 c1v = *(const float4*)&sctx[(h * 32 + d0 + 1) * 32 + q4 * 4];
        s0 += wo[q4 * 4 + 0] * c0v.x + wo[q4 * 4 + 1] * c0v.y
            + wo[q4 * 4 + 2] * c0v.z + wo[q4 * 4 + 3] * c0v.w;
        s1 += wo[q4 * 4 + 0] * c1v.x + wo[q4 * 4 + 1] * c1v.y
            + wo[q4 * 4 + 2] * c1v.z + wo[q4 * 4 + 3] * c1v.w;
    }
    float* Mout = g_M + (size_t)b * HIDDEN * HIDDEN + o * HIDDEN;
    Mout[col0]     = s0 * sinv[col0];
    Mout[col0 + 1] = s1 * sinv[col0 + 1];
}

// ---------------- K4: tf32 mma y = M_b @ softq + bo, + stats ----------------
// grid (32 ncol, 32 b), 256 threads, double-buffered
__global__ void __launch_bounds__(256) k4_out(const float* __restrict__ bo)
{
    __shared__ float sAb[2 * SLAB];
    __shared__ float sBb[2 * SLAB];
    __shared__ float redS[8], redQ[8];

    const int b  = blockIdx.y;
    const int n0 = blockIdx.x * 128;
    const int tid = threadIdx.x;
    const int lane = tid & 31, wid = tid >> 5;
    const int mbase = (wid >> 2) * 64, nbase = (wid & 3) * 32;
    const int gid = lane >> 2, tig = lane & 3;

    const float* Mb = g_M + (size_t)b * HIDDEN * HIDDEN;
    const float* qb = g_qkv + (size_t)b * 384 * NN + n0;

    const int arow = tid & 127, ah = tid >> 7;
    const int bk = tid >> 4, bn = (tid & 15) * 8;

    Frag f;
#pragma unroll
    for (int mt = 0; mt < 4; mt++)
#pragma unroll
        for (int nt = 0; nt < 4; nt++)
#pragma unroll
            for (int r = 0; r < 4; r++) f.d[mt][nt][r] = 0.f;

    float4 w0 = *(const float4*)&Mb[arow * 128 + ah * 8];
    float4 w1 = *(const float4*)&Mb[arow * 128 + ah * 8 + 4];
    float4 x0 = *(const float4*)&qb[(size_t)bk * NN + bn];
    float4 x1 = *(const float4*)&qb[(size_t)bk * NN + bn + 4];
    stage_store(sAb, sBb, arow, ah, bk, bn, w0, w1, x0, x1);
    __syncthreads();

    for (int kt = 0; kt < 8; kt++) {
        const int cur = kt & 1;
        if (kt < 7) {
            const int k0 = (kt + 1) * 16;
            w0 = *(const float4*)&Mb[arow * 128 + k0 + ah * 8];
            w1 = *(const float4*)&Mb[arow * 128 + k0 + ah * 8 + 4];
            x0 = *(const float4*)&qb[(size_t)(k0 + bk) * NN + bn];
            x1 = *(const float4*)&qb[(size_t)(k0 + bk) * NN + bn + 4];
        }
        slab_mma(f, sAb + cur * SLAB, sBb + cur * SLAB, mbase, nbase, gid, tig);
        if (kt < 7) {
            stage_store(sAb + (1 - cur) * SLAB, sBb + (1 - cur) * SLAB,
                        arow, ah, bk, bn, w0, w1, x0, x1);
            __syncthreads();
        }
    }

    float* outp = g_y + (size_t)b * C * NN + n0;
    float lsum = 0.f, lsq = 0.f;
#pragma unroll
    for (int mt = 0; mt < 4; mt++) {
        int row = mbase + mt * 16 + gid;
        float bb0 = bo[row], bb8 = bo[row + 8];
#pragma unroll
        for (int nt = 0; nt < 4; nt++) {
            int col = nbase + nt * 8 + tig * 2;
            float v0 = f.d[mt][nt][0] + bb0, v1 = f.d[mt][nt][1] + bb0;
            float v2 = f.d[mt][nt][2] + bb8, v3 = f.d[mt][nt][3] + bb8;
            *(float2*)&outp[(size_t)row * NN + col] = make_float2(v0, v1);
            *(float2*)&outp[(size_t)(row + 8) * NN + col] = make_float2(v2, v3);
            lsum += v0 + v1 + v2 + v3;
            lsq  += v0 * v0 + v1 * v1 + v2 * v2 + v3 * v3;
        }
    }
    const int w = tid >> 5;
#pragma unroll
    for (int o = 16; o; o >>= 1) {
        lsum += __shfl_xor_sync(0xffffffffu, lsum, o);
        lsq  += __shfl_xor_sync(0xffffffffu, lsq,  o);
    }
    if (lane == 0) { redS[w] = lsum; redQ[w] = lsq; }
    __syncthreads();
    if (tid == 0) {
        float s = 0.f, q = 0.f;
#pragma unroll
        for (int i = 0; i < 8; i++) { s += redS[i]; q += redQ[i]; }
        atomicAdd(&g_sum[b], s);
        atomicAdd(&g_sumsq[b], q);
    }
}

// ---------------- K5: GroupNorm, float4 ----------------
__global__ void __launch_bounds__(256) k5_norm(
    const float* __restrict__ gn_w, const float* __restrict__ gn_b,
    float* __restrict__ out)
{
    int i4 = blockIdx.x * 256 + threadIdx.x;
    int b = i4 >> 17;
    int c = (i4 >> 10) & 127;
    const float cn = (float)(C * NN);
    float mu = g_sum[b] / cn;
    float var = g_sumsq[b] / cn - mu * mu;
    float is = rsqrtf(var + GEPS);
    float w = gn_w[c] * is, bb = gn_b[c] - mu * w;
    float4 v = *(const float4*)&g_y[(size_t)i4 * 4];
    v.x = v.x * w + bb; v.y = v.y * w + bb;
    v.z = v.z * w + bb; v.w = v.w * w + bb;
    *(float4*)&out[(size_t)i4 * 4] = v;
}

// ---------------- launch ----------------
extern "C" void kernel_launch(void* const* d_in, const int* in_sizes, int n_in,
                              void* d_out, int out_size)
{
    const float* x  = (const float*)d_in[0];
    const float* Wq = (const float*)d_in[1];
    const float* Wk = (const float*)d_in[2];
    const float* Wv = (const float*)d_in[3];
    const float* Wo = (const float*)d_in[4];
    const float* bo = (const float*)d_in[5];
    const float* gw = (const float*)d_in[6];
    const float* gb = (const float*)d_in[7];
    float* out = (float*)d_out;

    static int smem_set = 0;
    const int K1_SMEM = 128 * 132 * 4;   // 67584 B: q staging (mainloop uses 33.8KB)
    if (!smem_set) {
        cudaFuncSetAttribute(k1_proj, cudaFuncAttributeMaxDynamicSharedMemorySize, K1_SMEM);
        smem_set = 1;
    }

    k0_zero<<<132, 256>>>();
    k1_proj<<<dim3(32, 3, 32), 256, K1_SMEM>>>(x, Wq, Wk, Wv);
    k2_ctx<<<dim3(8, 128), 256>>>();
    k3_fold<<<dim3(32, 32), 256>>>(Wo);
    k4_out<<<dim3(32, 32), 256>>>(bo);
    k5_norm<<<16384, 256>>>(gw, gb, out);
}

// round 7
// speedup vs baseline: 1.2211x; 1.2211x over previous
#include <cuda_runtime.h>
#include <cstdint>
#include <math.h>

#define B 32
#define C 128
#define NN 4096
#define HEADS 4
#define DH 32
#define HIDDEN 128
#define QSCALE 0.17677669529663687f   /* 32^-0.5 */
#define GEPS 1e-5f

// ---------------- scratch ----------------
__device__ float g_qkv[(size_t)B * 384 * NN];  // 0-127 q (softmaxed), 128-255 k, 256-383 v
__device__ float g_ctx[B * HEADS * DH * DH];   // unnormalized ctx partials
__device__ float g_rsum[B * HIDDEN];           // per (b, row) sum of exp(k)
__device__ float g_M[B * HIDDEN * HIDDEN];
__device__ float g_y[(size_t)B * C * NN];
__device__ float g_sum[B];
__device__ float g_sumsq[B];

__device__ __forceinline__ uint32_t pack_bf16(float lo, float hi) {
    uint32_t r;
    asm("cvt.rn.bf16x2.f32 %0, %1, %2;" : "=r"(r) : "f"(hi), "f"(lo));
    return r;
}

__device__ __forceinline__ void mma_bf16(float* d, const uint32_t* a, const uint32_t* b) {
    asm("mma.sync.aligned.m16n8k16.row.col.f32.bf16.bf16.f32 "
        "{%0,%1,%2,%3}, {%4,%5,%6,%7}, {%8,%9}, {%0,%1,%2,%3};"
        : "+f"(d[0]), "+f"(d[1]), "+f"(d[2]), "+f"(d[3])
        : "r"(a[0]), "r"(a[1]), "r"(a[2]), "r"(a[3]), "r"(b[0]), "r"(b[1]));
}

// ---------------- K0: zero accumulators ----------------
__global__ void __launch_bounds__(256) k0_zero() {
    int gid = blockIdx.x * 256 + threadIdx.x;
    float4 z = make_float4(0.f, 0.f, 0.f, 0.f);
    if (gid < 32768) ((float4*)g_ctx)[gid] = z;
    if (gid < 1024)  ((float4*)g_rsum)[gid] = z;
    if (gid < 32) { g_sum[gid] = 0.f; g_sumsq[gid] = 0.f; }
}

// ---------------- bf16 mma mainloop helpers ----------------
// K slab = 16 -> 8 bf16x2 "pair rows", stride 136 u32 (bank = 8*pair+idx, conflict-free)
#define PSTRIDE 136
#define SLAB_U32 (8 * PSTRIDE)   /* 1088 */

struct Frag { float d[4][4][4]; };

// A: [128 rows][k slab 16] -> sA[pair][row]
__device__ __forceinline__ void stage_A(
    uint32_t* sA, int arow, int ah, const float4& w0, const float4& w1)
{
    sA[(ah * 4 + 0) * PSTRIDE + arow] = pack_bf16(w0.x, w0.y);
    sA[(ah * 4 + 1) * PSTRIDE + arow] = pack_bf16(w0.z, w0.w);
    sA[(ah * 4 + 2) * PSTRIDE + arow] = pack_bf16(w1.x, w1.y);
    sA[(ah * 4 + 3) * PSTRIDE + arow] = pack_bf16(w1.z, w1.w);
}
// B: two k rows fused -> sB[pair][col], uint4 store
__device__ __forceinline__ void stage_B(
    uint32_t* sB, int pk, int bn, const float4& x0, const float4& x1)
{
    uint4 p;
    p.x = pack_bf16(x0.x, x1.x);
    p.y = pack_bf16(x0.y, x1.y);
    p.z = pack_bf16(x0.z, x1.z);
    p.w = pack_bf16(x0.w, x1.w);
    *(uint4*)&sB[pk * PSTRIDE + bn] = p;
}

__device__ __forceinline__ void slab_mma(
    Frag& f, const uint32_t* sA, const uint32_t* sB,
    int mbase, int nbase, int gid, int tig)
{
    uint32_t a[4][4], bf[4][2];
#pragma unroll
    for (int mt = 0; mt < 4; mt++) {
        int row = mbase + mt * 16 + gid;
        a[mt][0] = sA[tig * PSTRIDE + row];
        a[mt][1] = sA[tig * PSTRIDE + row + 8];
        a[mt][2] = sA[(tig + 4) * PSTRIDE + row];
        a[mt][3] = sA[(tig + 4) * PSTRIDE + row + 8];
    }
#pragma unroll
    for (int nt = 0; nt < 4; nt++) {
        int col = nbase + nt * 8 + gid;
        bf[nt][0] = sB[tig * PSTRIDE + col];
        bf[nt][1] = sB[(tig + 4) * PSTRIDE + col];
    }
#pragma unroll
    for (int mt = 0; mt < 4; mt++)
#pragma unroll
        for (int nt = 0; nt < 4; nt++)
            mma_bf16(f.d[mt][nt], a[mt], bf[nt]);
}

// ---------------- K1: bf16 mma qkv projection + fused q softmax ----------------
// grid (32 ncol, 3 rowtile, 32 b), 256 threads (8 warps, 2x4)
__global__ void __launch_bounds__(256) k1_proj(
    const float* __restrict__ x,
    const float* __restrict__ Wq,
    const float* __restrict__ Wk,
    const float* __restrict__ Wv)
{
    __shared__ uint32_t sA[2 * SLAB_U32];
    __shared__ uint32_t sB[2 * SLAB_U32];
    extern __shared__ float stage[];   // [128][132] q epilogue

    const int b  = blockIdx.z;
    const int rowtile = blockIdx.y;
    const int n0 = blockIdx.x * 128;
    const int tid = threadIdx.x;
    const int lane = tid & 31, wid = tid >> 5;
    const int mbase = (wid >> 2) * 64, nbase = (wid & 3) * 32;
    const int gid = lane >> 2, tig = lane & 3;

    const float* Wp = (rowtile == 0) ? Wq : ((rowtile == 1) ? Wk : Wv);
    const float* xb = x + (size_t)b * C * NN + n0;

    const int arow = tid & 127, ah = tid >> 7;   // A loader
    const int pk = tid >> 5, bn = (tid & 31) * 4; // B loader (pair rows)

    Frag f;
#pragma unroll
    for (int mt = 0; mt < 4; mt++)
#pragma unroll
        for (int nt = 0; nt < 4; nt++)
#pragma unroll
            for (int r = 0; r < 4; r++) f.d[mt][nt][r] = 0.f;

    // preload slab 0
    float4 w0 = *(const float4*)&Wp[arow * 128 + ah * 8];
    float4 w1 = *(const float4*)&Wp[arow * 128 + ah * 8 + 4];
    float4 x0 = *(const float4*)&xb[(size_t)(2 * pk) * NN + bn];
    float4 x1 = *(const float4*)&xb[(size_t)(2 * pk + 1) * NN + bn];
    stage_A(sA, arow, ah, w0, w1);
    stage_B(sB, pk, bn, x0, x1);
    __syncthreads();

    for (int kt = 0; kt < 8; kt++) {
        const int cur = kt & 1;
        if (kt < 7) {
            const int k0 = (kt + 1) * 16;
            w0 = *(const float4*)&Wp[arow * 128 + k0 + ah * 8];
            w1 = *(const float4*)&Wp[arow * 128 + k0 + ah * 8 + 4];
            x0 = *(const float4*)&xb[(size_t)(k0 + 2 * pk) * NN + bn];
            x1 = *(const float4*)&xb[(size_t)(k0 + 2 * pk + 1) * NN + bn];
        }
        slab_mma(f, sA + cur * SLAB_U32, sB + cur * SLAB_U32, mbase, nbase, gid, tig);
        if (kt < 7) {
            stage_A(sA + (1 - cur) * SLAB_U32, arow, ah, w0, w1);
            stage_B(sB + (1 - cur) * SLAB_U32, pk, bn, x0, x1);
            __syncthreads();
        }
    }

    if (rowtile != 0) {
        float* outp = g_qkv + ((size_t)b * 384 + rowtile * 128) * NN + n0;
#pragma unroll
        for (int mt = 0; mt < 4; mt++) {
#pragma unroll
            for (int nt = 0; nt < 4; nt++) {
                int row = mbase + mt * 16 + gid;
                int col = nbase + nt * 8 + tig * 2;
                *(float2*)&outp[(size_t)row * NN + col] =
                    make_float2(f.d[mt][nt][0], f.d[mt][nt][1]);
                *(float2*)&outp[(size_t)(row + 8) * NN + col] =
                    make_float2(f.d[mt][nt][2], f.d[mt][nt][3]);
            }
        }
        return;
    }

    // q: stage -> softmax over d per (h, col) -> coalesced global write
    __syncthreads();
#pragma unroll
    for (int mt = 0; mt < 4; mt++) {
#pragma unroll
        for (int nt = 0; nt < 4; nt++) {
            int row = mbase + mt * 16 + gid;
            int col = nbase + nt * 8 + tig * 2;
            *(float2*)&stage[row * 132 + col] = make_float2(f.d[mt][nt][0], f.d[mt][nt][1]);
            *(float2*)&stage[(row + 8) * 132 + col] = make_float2(f.d[mt][nt][2], f.d[mt][nt][3]);
        }
    }
    __syncthreads();

    float* outq = g_qkv + (size_t)b * 384 * NN + n0;
#pragma unroll
    for (int t = tid; t < 512; t += 256) {
        const int col = t & 127;
        const int h = t >> 7;
        float sum = 0.f;
#pragma unroll
        for (int dd = 0; dd < 32; dd++) {
            float* p = &stage[(h * 32 + dd) * 132 + col];
            float e = __expf(*p);
            *p = e;
            sum += e;
        }
        float inv = QSCALE / sum;
#pragma unroll
        for (int dd = 0; dd < 32; dd++)
            outq[(size_t)(h * 32 + dd) * NN + col] = stage[(h * 32 + dd) * 132 + col] * inv;
    }
}

// ---------------- K2: partial ctx = exp(k) @ v^T + partial rowsum ----------------
__global__ void __launch_bounds__(256) k2_ctx()
{
    const int bh = blockIdx.y;
    const int b = bh >> 2, h = bh & 3;
    const int cbase = blockIdx.x * 512;
    const float* kb = g_qkv + ((size_t)b * 384 + 128 + h * 32) * NN + cbase;
    const float* vb = g_qkv + ((size_t)b * 384 + 256 + h * 32) * NN + cbase;

    __shared__ float sK[32 * 128];
    __shared__ float sVT[128 * 36];

    const int tid = threadIdx.x;
    const int d  = tid >> 3;
    const int e0 = (tid & 7) * 4;
    const int ld_row = tid >> 3;
    const int ld_c   = (tid & 7) * 16;

    float4 acc = make_float4(0.f, 0.f, 0.f, 0.f);
    float lsum = 0.f;

    for (int c0 = 0; c0 < 512; c0 += 128) {
        __syncthreads();
        {
            const float* kr = kb + (size_t)ld_row * NN + c0 + ld_c;
#pragma unroll
            for (int q4 = 0; q4 < 4; q4++) {
                float4 t = *(const float4*)(kr + q4 * 4);
                float e0v = __expf(t.x), e1v = __expf(t.y);
                float e2v = __expf(t.z), e3v = __expf(t.w);
                int base = ld_row * 128 + ld_c + q4 * 4;
                sK[base + 0] = e0v; sK[base + 1] = e1v;
                sK[base + 2] = e2v; sK[base + 3] = e3v;
                lsum += e0v + e1v + e2v + e3v;
            }
            const float* vr = vb + (size_t)ld_row * NN + c0 + ld_c;
#pragma unroll
            for (int q4 = 0; q4 < 4; q4++) {
                float4 t = *(const float4*)(vr + q4 * 4);
                int nc = ld_c + q4 * 4;
                sVT[(nc + 0) * 36 + ld_row] = t.x;
                sVT[(nc + 1) * 36 + ld_row] = t.y;
                sVT[(nc + 2) * 36 + ld_row] = t.z;
                sVT[(nc + 3) * 36 + ld_row] = t.w;
            }
        }
        __syncthreads();
#pragma unroll 4
        for (int n = 0; n < 128; n++) {
            float kd = sK[d * 128 + n];
            float4 vv = *(const float4*)&sVT[n * 36 + e0];
            acc.x += kd * vv.x; acc.y += kd * vv.y;
            acc.z += kd * vv.z; acc.w += kd * vv.w;
        }
    }

#pragma unroll
    for (int o = 4; o; o >>= 1) lsum += __shfl_xor_sync(0xffffffffu, lsum, o);
    if ((tid & 7) == 0)
        atomicAdd(&g_rsum[b * HIDDEN + h * 32 + ld_row], lsum);

    float* cp = &g_ctx[((size_t)bh * 32 + d) * 32 + e0];
    atomicAdd(cp + 0, acc.x);
    atomicAdd(cp + 1, acc.y);
    atomicAdd(cp + 2, acc.z);
    atomicAdd(cp + 3, acc.w);
}

// ---------------- K3: M_b = Wo @ blockdiag(ctx^T / rsum) ----------------
__global__ void __launch_bounds__(256) k3_fold(const float* __restrict__ Wo)
{
    const int b = blockIdx.y;
    const int og = blockIdx.x * 4;
    __shared__ float sctx[HEADS * DH * DH];
    __shared__ float sinv[HIDDEN];
    const int tid = threadIdx.x;
#pragma unroll
    for (int rr = 0; rr < 4; rr++) {
        int idx = tid + rr * 256;
        *(float4*)&sctx[idx * 4] = *(const float4*)&g_ctx[(size_t)b * 4096 + idx * 4];
    }
    if (tid < 128) sinv[tid] = 1.0f / g_rsum[b * HIDDEN + tid];
    __syncthreads();

    const int o = og + (tid >> 6);
    const int col0 = (tid & 63) * 2;
    const int h = col0 >> 5;
    const int d0 = col0 & 31;

    float wo[32];
#pragma unroll
    for (int q4 = 0; q4 < 8; q4++) {
        float4 t = *(const float4*)&Wo[o * 128 + h * 32 + q4 * 4];
        wo[q4 * 4 + 0] = t.x; wo[q4 * 4 + 1] = t.y;
        wo[q4 * 4 + 2] = t.z; wo[q4 * 4 + 3] = t.w;
    }
    float s0 = 0.f, s1 = 0.f;
#pragma unroll
    for (int q4 = 0; q4 < 8; q4++) {
        float4 c0v = *(const float4*)&sctx[(h * 32 + d0) * 32 + q4 * 4];
        float4 c1v = *(const float4*)&sctx[(h * 32 + d0 + 1) * 32 + q4 * 4];
        s0 += wo[q4 * 4 + 0] * c0v.x + wo[q4 * 4 + 1] * c0v.y
            + wo[q4 * 4 + 2] * c0v.z + wo[q4 * 4 + 3] * c0v.w;
        s1 += wo[q4 * 4 + 0] * c1v.x + wo[q4 * 4 + 1] * c1v.y
            + wo[q4 * 4 + 2] * c1v.z + wo[q4 * 4 + 3] * c1v.w;
    }
    float* Mout = g_M + (size_t)b * HIDDEN * HIDDEN + o * HIDDEN;
    Mout[col0]     = s0 * sinv[col0];
    Mout[col0 + 1] = s1 * sinv[col0 + 1];
}

// ---------------- K4: bf16 mma y = M_b @ softq + bo, + stats ----------------
// grid (32 ncol, 32 b), 256 threads, double-buffered
__global__ void __launch_bounds__(256) k4_out(const float* __restrict__ bo)
{
    __shared__ uint32_t sA[2 * SLAB_U32];
    __shared__ uint32_t sB[2 * SLAB_U32];
    __shared__ float redS[8], redQ[8];

    const int b  = blockIdx.y;
    const int n0 = blockIdx.x * 128;
    const int tid = threadIdx.x;
    const int lane = tid & 31, wid = tid >> 5;
    const int mbase = (wid >> 2) * 64, nbase = (wid & 3) * 32;
    const int gid = lane >> 2, tig = lane & 3;

    const float* Mb = g_M + (size_t)b * HIDDEN * HIDDEN;
    const float* qb = g_qkv + (size_t)b * 384 * NN + n0;

    const int arow = tid & 127, ah = tid >> 7;
    const int pk = tid >> 5, bn = (tid & 31) * 4;

    Frag f;
#pragma unroll
    for (int mt = 0; mt < 4; mt++)
#pragma unroll
        for (int nt = 0; nt < 4; nt++)
#pragma unroll
            for (int r = 0; r < 4; r++) f.d[mt][nt][r] = 0.f;

    float4 w0 = *(const float4*)&Mb[arow * 128 + ah * 8];
    float4 w1 = *(const float4*)&Mb[arow * 128 + ah * 8 + 4];
    float4 x0 = *(const float4*)&qb[(size_t)(2 * pk) * NN + bn];
    float4 x1 = *(const float4*)&qb[(size_t)(2 * pk + 1) * NN + bn];
    stage_A(sA, arow, ah, w0, w1);
    stage_B(sB, pk, bn, x0, x1);
    __syncthreads();

    for (int kt = 0; kt < 8; kt++) {
        const int cur = kt & 1;
        if (kt < 7) {
            const int k0 = (kt + 1) * 16;
            w0 = *(const float4*)&Mb[arow * 128 + k0 + ah * 8];
            w1 = *(const float4*)&Mb[arow * 128 + k0 + ah * 8 + 4];
            x0 = *(const float4*)&qb[(size_t)(k0 + 2 * pk) * NN + bn];
            x1 = *(const float4*)&qb[(size_t)(k0 + 2 * pk + 1) * NN + bn];
        }
        slab_mma(f, sA + cur * SLAB_U32, sB + cur * SLAB_U32, mbase, nbase, gid, tig);
        if (kt < 7) {
            stage_A(sA + (1 - cur) * SLAB_U32, arow, ah, w0, w1);
            stage_B(sB + (1 - cur) * SLAB_U32, pk, bn, x0, x1);
            __syncthreads();
        }
    }

    float* outp = g_y + (size_t)b * C * NN + n0;
    float lsum = 0.f, lsq = 0.f;
#pragma unroll
    for (int mt = 0; mt < 4; mt++) {
        int row = mbase + mt * 16 + gid;
        float bb0 = bo[row], bb8 = bo[row + 8];
#pragma unroll
        for (int nt = 0; nt < 4; nt++) {
            int col = nbase + nt * 8 + tig * 2;
            float v0 = f.d[mt][nt][0] + bb0, v1 = f.d[mt][nt][1] + bb0;
            float v2 = f.d[mt][nt][2] + bb8, v3 = f.d[mt][nt][3] + bb8;
            *(float2*)&outp[(size_t)row * NN + col] = make_float2(v0, v1);
            *(float2*)&outp[(size_t)(row + 8) * NN + col] = make_float2(v2, v3);
            lsum += v0 + v1 + v2 + v3;
            lsq  += v0 * v0 + v1 * v1 + v2 * v2 + v3 * v3;
        }
    }
    const int w = tid >> 5;
#pragma unroll
    for (int o = 16; o; o >>= 1) {
        lsum += __shfl_xor_sync(0xffffffffu, lsum, o);
        lsq  += __shfl_xor_sync(0xffffffffu, lsq,  o);
    }
    if (lane == 0) { redS[w] = lsum; redQ[w] = lsq; }
    __syncthreads();
    if (tid == 0) {
        float s = 0.f, q = 0.f;
#pragma unroll
        for (int i = 0; i < 8; i++) { s += redS[i]; q += redQ[i]; }
        atomicAdd(&g_sum[b], s);
        atomicAdd(&g_sumsq[b], q);
    }
}

// ---------------- K5: GroupNorm, float4 ----------------
__global__ void __launch_bounds__(256) k5_norm(
    const float* __restrict__ gn_w, const float* __restrict__ gn_b,
    float* __restrict__ out)
{
    int i4 = blockIdx.x * 256 + threadIdx.x;
    int b = i4 >> 17;
    int c = (i4 >> 10) & 127;
    const float cn = (float)(C * NN);
    float mu = g_sum[b] / cn;
    float var = g_sumsq[b] / cn - mu * mu;
    float is = rsqrtf(var + GEPS);
    float w = gn_w[c] * is, bb = gn_b[c] - mu * w;
    float4 v = *(const float4*)&g_y[(size_t)i4 * 4];
    v.x = v.x * w + bb; v.y = v.y * w + bb;
    v.z = v.z * w + bb; v.w = v.w * w + bb;
    *(float4*)&out[(size_t)i4 * 4] = v;
}

// ---------------- launch ----------------
extern "C" void kernel_launch(void* const* d_in, const int* in_sizes, int n_in,
                              void* d_out, int out_size)
{
    const float* x  = (const float*)d_in[0];
    const float* Wq = (const float*)d_in[1];
    const float* Wk = (const float*)d_in[2];
    const float* Wv = (const float*)d_in[3];
    const float* Wo = (const float*)d_in[4];
    const float* bo = (const float*)d_in[5];
    const float* gw = (const float*)d_in[6];
    const float* gb = (const float*)d_in[7];
    float* out = (float*)d_out;

    static int smem_set = 0;
    const int K1_SMEM = 128 * 132 * 4;   // 67584 B: q staging (dynamic)
    if (!smem_set) {
        cudaFuncSetAttribute(k1_proj, cudaFuncAttributeMaxDynamicSharedMemorySize, K1_SMEM);
        smem_set = 1;
    }

    k0_zero<<<132, 256>>>();
    k1_proj<<<dim3(32, 3, 32), 256, K1_SMEM>>>(x, Wq, Wk, Wv);
    k2_ctx<<<dim3(8, 128), 256>>>();
    k3_fold<<<dim3(32, 32), 256>>>(Wo);
    k4_out<<<dim3(32, 32), 256>>>(bo);
    k5_norm<<<16384, 256>>>(gw, gb, out);
}

// round 8
// speedup vs baseline: 1.2361x; 1.0123x over previous
#include <cuda_runtime.h>
#include <cstdint>
#include <math.h>

#define B 32
#define C 128
#define NN 4096
#define HEADS 4
#define DH 32
#define HIDDEN 128
#define QSCALE 0.17677669529663687f   /* 32^-0.5 */
#define GEPS 1e-5f

// ---------------- scratch ----------------
__device__ float g_qkv[(size_t)B * 384 * NN];  // 0-127 q (softmaxed), 128-255 k, 256-383 v
__device__ float g_ctx[B * HEADS * DH * DH];   // unnormalized ctx partials
__device__ float g_rsum[B * HIDDEN];           // per (b, row) sum of exp(k)
__device__ float g_M[B * HIDDEN * HIDDEN];
__device__ float g_y[(size_t)B * C * NN];
__device__ float g_sum[B];
__device__ float g_sumsq[B];

__device__ __forceinline__ uint32_t pack_bf16(float lo, float hi) {
    uint32_t r;
    asm("cvt.rn.bf16x2.f32 %0, %1, %2;" : "=r"(r) : "f"(hi), "f"(lo));
    return r;
}

__device__ __forceinline__ void mma_bf16(float* d, const uint32_t* a, const uint32_t* b) {
    asm("mma.sync.aligned.m16n8k16.row.col.f32.bf16.bf16.f32 "
        "{%0,%1,%2,%3}, {%4,%5,%6,%7}, {%8,%9}, {%0,%1,%2,%3};"
        : "+f"(d[0]), "+f"(d[1]), "+f"(d[2]), "+f"(d[3])
        : "r"(a[0]), "r"(a[1]), "r"(a[2]), "r"(a[3]), "r"(b[0]), "r"(b[1]));
}

// ---------------- K0: zero accumulators ----------------
__global__ void __launch_bounds__(256) k0_zero() {
    int gid = blockIdx.x * 256 + threadIdx.x;
    float4 z = make_float4(0.f, 0.f, 0.f, 0.f);
    if (gid < 32768) ((float4*)g_ctx)[gid] = z;
    if (gid < 1024)  ((float4*)g_rsum)[gid] = z;
    if (gid < 32) { g_sum[gid] = 0.f; g_sumsq[gid] = 0.f; }
}

// ---------------- bf16 mma helpers ----------------
// pair-row stride 136 u32 -> conflict-free fragment LDS
#define PSTRIDE 136
#define SLAB_U32 (8 * PSTRIDE)     /* one K=16 slab: 8 pair rows */
#define X_U32    (64 * PSTRIDE)    /* full 128-k x tile: 64 pair rows */

struct Frag { float d[4][4][4]; };

__device__ __forceinline__ void stage_A(
    uint32_t* sA, int arow, int ah, const float4& w0, const float4& w1)
{
    sA[(ah * 4 + 0) * PSTRIDE + arow] = pack_bf16(w0.x, w0.y);
    sA[(ah * 4 + 1) * PSTRIDE + arow] = pack_bf16(w0.z, w0.w);
    sA[(ah * 4 + 2) * PSTRIDE + arow] = pack_bf16(w1.x, w1.y);
    sA[(ah * 4 + 3) * PSTRIDE + arow] = pack_bf16(w1.z, w1.w);
}

__device__ __forceinline__ void slab_mma(
    Frag& f, const uint32_t* sA, const uint32_t* sB,
    int mbase, int nbase, int gid, int tig)
{
    uint32_t a[4][4], bf[4][2];
#pragma unroll
    for (int mt = 0; mt < 4; mt++) {
        int row = mbase + mt * 16 + gid;
        a[mt][0] = sA[tig * PSTRIDE + row];
        a[mt][1] = sA[tig * PSTRIDE + row + 8];
        a[mt][2] = sA[(tig + 4) * PSTRIDE + row];
        a[mt][3] = sA[(tig + 4) * PSTRIDE + row + 8];
    }
#pragma unroll
    for (int nt = 0; nt < 4; nt++) {
        int col = nbase + nt * 8 + gid;
        bf[nt][0] = sB[tig * PSTRIDE + col];
        bf[nt][1] = sB[(tig + 4) * PSTRIDE + col];
    }
#pragma unroll
    for (int mt = 0; mt < 4; mt++)
#pragma unroll
        for (int nt = 0; nt < 4; nt++)
            mma_bf16(f.d[mt][nt], a[mt], bf[nt]);
}

// ---------------- K1: fused qkv projection, x staged ONCE ----------------
// grid (32 ncol, 32 b), 256 threads (8 warps, 2x4); rt order k,v,q (q last)
__global__ void __launch_bounds__(256) k1_fused(
    const float* __restrict__ x,
    const float* __restrict__ Wq,
    const float* __restrict__ Wk,
    const float* __restrict__ Wv)
{
    extern __shared__ uint32_t dsm[];
    uint32_t* sA = dsm;                   // 2 x SLAB_U32 (W slabs, double buffered)
    uint32_t* sX = dsm + 2 * SLAB_U32;    // X_U32 (full x tile as bf16x2)
    float* stage = (float*)dsm;           // aliased [128][132] for q epilogue (last rt only)

    const int b  = blockIdx.y;
    const int n0 = blockIdx.x * 128;
    const int tid = threadIdx.x;
    const int lane = tid & 31, wid = tid >> 5;
    const int mbase = (wid >> 2) * 64, nbase = (wid & 3) * 32;
    const int gid = lane >> 2, tig = lane & 3;

    const float* xb = x + (size_t)b * C * NN + n0;
    const int arow = tid & 127, ah = tid >> 7;

    // ---- stage full x tile (128 k x 128 n) as bf16 pairs ----
    {
        const int colg = (tid & 31) * 4;
        const int pr0 = tid >> 5;
#pragma unroll
        for (int i = 0; i < 8; i++) {
            int pair = i * 8 + pr0;
            float4 x0 = *(const float4*)&xb[(size_t)(2 * pair) * NN + colg];
            float4 x1 = *(const float4*)&xb[(size_t)(2 * pair + 1) * NN + colg];
            uint4 p;
            p.x = pack_bf16(x0.x, x1.x);
            p.y = pack_bf16(x0.y, x1.y);
            p.z = pack_bf16(x0.z, x1.z);
            p.w = pack_bf16(x0.w, x1.w);
            *(uint4*)&sX[pair * PSTRIDE + colg] = p;
        }
    }
    __syncthreads();

#pragma unroll 1
    for (int rti = 0; rti < 3; rti++) {
        const int rt = (rti + 1) % 3;   // 1 (k), 2 (v), 0 (q last)
        const float* Wp = (rt == 0) ? Wq : ((rt == 1) ? Wk : Wv);

        Frag f;
#pragma unroll
        for (int mt = 0; mt < 4; mt++)
#pragma unroll
            for (int nt = 0; nt < 4; nt++)
#pragma unroll
                for (int r = 0; r < 4; r++) f.d[mt][nt][r] = 0.f;

        // preload W slab 0
        float4 w0 = *(const float4*)&Wp[arow * 128 + ah * 8];
        float4 w1 = *(const float4*)&Wp[arow * 128 + ah * 8 + 4];
        stage_A(sA, arow, ah, w0, w1);
        __syncthreads();

        for (int kt = 0; kt < 8; kt++) {
            const int cur = kt & 1;
            if (kt < 7) {
                const int k0 = (kt + 1) * 16;
                w0 = *(const float4*)&Wp[arow * 128 + k0 + ah * 8];
                w1 = *(const float4*)&Wp[arow * 128 + k0 + ah * 8 + 4];
            }
            slab_mma(f, sA + cur * SLAB_U32, sX + kt * SLAB_U32, mbase, nbase, gid, tig);
            if (kt < 7) {
                stage_A(sA + (1 - cur) * SLAB_U32, arow, ah, w0, w1);
                __syncthreads();
            }
        }

        if (rt != 0) {
            float* outp = g_qkv + ((size_t)b * 384 + rt * 128) * NN + n0;
#pragma unroll
            for (int mt = 0; mt < 4; mt++) {
#pragma unroll
                for (int nt = 0; nt < 4; nt++) {
                    int row = mbase + mt * 16 + gid;
                    int col = nbase + nt * 8 + tig * 2;
                    *(float2*)&outp[(size_t)row * NN + col] =
                        make_float2(f.d[mt][nt][0], f.d[mt][nt][1]);
                    *(float2*)&outp[(size_t)(row + 8) * NN + col] =
                        make_float2(f.d[mt][nt][2], f.d[mt][nt][3]);
                }
            }
            __syncthreads();   // all warps done with this rt's slab reads before next preload
            continue;
        }

        // rt == 0 (q, final pass): stage -> softmax over d -> coalesced write.
        // stage aliases sA/sX — safe, x no longer needed.
        __syncthreads();
#pragma unroll
        for (int mt = 0; mt < 4; mt++) {
#pragma unroll
            for (int nt = 0; nt < 4; nt++) {
                int row = mbase + mt * 16 + gid;
                int col = nbase + nt * 8 + tig * 2;
                *(float2*)&stage[row * 132 + col] =
                    make_float2(f.d[mt][nt][0], f.d[mt][nt][1]);
                *(float2*)&stage[(row + 8) * 132 + col] =
                    make_float2(f.d[mt][nt][2], f.d[mt][nt][3]);
            }
        }
        __syncthreads();

        float* outq = g_qkv + (size_t)b * 384 * NN + n0;
#pragma unroll
        for (int t = tid; t < 512; t += 256) {
            const int col = t & 127;
            const int h = t >> 7;
            float sum = 0.f;
#pragma unroll
            for (int dd = 0; dd < 32; dd++) {
                float* p = &stage[(h * 32 + dd) * 132 + col];
                float e = __expf(*p);
                *p = e;
                sum += e;
            }
            float inv = QSCALE / sum;
#pragma unroll
            for (int dd = 0; dd < 32; dd++)
                outq[(size_t)(h * 32 + dd) * NN + col] = stage[(h * 32 + dd) * 132 + col] * inv;
        }
    }
}

// ---------------- K2: partial ctx = exp(k) @ v^T + partial rowsum ----------------
__global__ void __launch_bounds__(256) k2_ctx()
{
    const int bh = blockIdx.y;
    const int b = bh >> 2, h = bh & 3;
    const int cbase = blockIdx.x * 512;
    const float* kb = g_qkv + ((size_t)b * 384 + 128 + h * 32) * NN + cbase;
    const float* vb = g_qkv + ((size_t)b * 384 + 256 + h * 32) * NN + cbase;

    __shared__ float sK[32 * 128];
    __shared__ float sVT[128 * 36];

    const int tid = threadIdx.x;
    const int d  = tid >> 3;
    const int e0 = (tid & 7) * 4;
    const int ld_row = tid >> 3;
    const int ld_c   = (tid & 7) * 16;

    float4 acc = make_float4(0.f, 0.f, 0.f, 0.f);
    float lsum = 0.f;

    for (int c0 = 0; c0 < 512; c0 += 128) {
        __syncthreads();
        {
            const float* kr = kb + (size_t)ld_row * NN + c0 + ld_c;
#pragma unroll
            for (int q4 = 0; q4 < 4; q4++) {
                float4 t = *(const float4*)(kr + q4 * 4);
                float e0v = __expf(t.x), e1v = __expf(t.y);
                float e2v = __expf(t.z), e3v = __expf(t.w);
                int base = ld_row * 128 + ld_c + q4 * 4;
                sK[base + 0] = e0v; sK[base + 1] = e1v;
                sK[base + 2] = e2v; sK[base + 3] = e3v;
                lsum += e0v + e1v + e2v + e3v;
            }
            const float* vr = vb + (size_t)ld_row * NN + c0 + ld_c;
#pragma unroll
            for (int q4 = 0; q4 < 4; q4++) {
                float4 t = *(const float4*)(vr + q4 * 4);
                int nc = ld_c + q4 * 4;
                sVT[(nc + 0) * 36 + ld_row] = t.x;
                sVT[(nc + 1) * 36 + ld_row] = t.y;
                sVT[(nc + 2) * 36 + ld_row] = t.z;
                sVT[(nc + 3) * 36 + ld_row] = t.w;
            }
        }
        __syncthreads();
#pragma unroll 4
        for (int n = 0; n < 128; n++) {
            float kd = sK[d * 128 + n];
            float4 vv = *(const float4*)&sVT[n * 36 + e0];
            acc.x += kd * vv.x; acc.y += kd * vv.y;
            acc.z += kd * vv.z; acc.w += kd * vv.w;
        }
    }

#pragma unroll
    for (int o = 4; o; o >>= 1) lsum += __shfl_xor_sync(0xffffffffu, lsum, o);
    if ((tid & 7) == 0)
        atomicAdd(&g_rsum[b * HIDDEN + h * 32 + ld_row], lsum);

    float* cp = &g_ctx[((size_t)bh * 32 + d) * 32 + e0];
    atomicAdd(cp + 0, acc.x);
    atomicAdd(cp + 1, acc.y);
    atomicAdd(cp + 2, acc.z);
    atomicAdd(cp + 3, acc.w);
}

// ---------------- K3: M_b = Wo @ blockdiag(ctx^T / rsum) ----------------
__global__ void __launch_bounds__(256) k3_fold(const float* __restrict__ Wo)
{
    const int b = blockIdx.y;
    const int og = blockIdx.x * 4;
    __shared__ float sctx[HEADS * DH * DH];
    __shared__ float sinv[HIDDEN];
    const int tid = threadIdx.x;
#pragma unroll
    for (int rr = 0; rr < 4; rr++) {
        int idx = tid + rr * 256;
        *(float4*)&sctx[idx * 4] = *(const float4*)&g_ctx[(size_t)b * 4096 + idx * 4];
    }
    if (tid < 128) sinv[tid] = 1.0f / g_rsum[b * HIDDEN + tid];
    __syncthreads();

    const int o = og + (tid >> 6);
    const int col0 = (tid & 63) * 2;
    const int h = col0 >> 5;
    const int d0 = col0 & 31;

    float wo[32];
#pragma unroll
    for (int q4 = 0; q4 < 8; q4++) {
        float4 t = *(const float4*)&Wo[o * 128 + h * 32 + q4 * 4];
        wo[q4 * 4 + 0] = t.x; wo[q4 * 4 + 1] = t.y;
        wo[q4 * 4 + 2] = t.z; wo[q4 * 4 + 3] = t.w;
    }
    float s0 = 0.f, s1 = 0.f;
#pragma unroll
    for (int q4 = 0; q4 < 8; q4++) {
        float4 c0v = *(const float4*)&sctx[(h * 32 + d0) * 32 + q4 * 4];
        float4 c1v = *(const float4*)&sctx[(h * 32 + d0 + 1) * 32 + q4 * 4];
        s0 += wo[q4 * 4 + 0] * c0v.x + wo[q4 * 4 + 1] * c0v.y
            + wo[q4 * 4 + 2] * c0v.z + wo[q4 * 4 + 3] * c0v.w;
        s1 += wo[q4 * 4 + 0] * c1v.x + wo[q4 * 4 + 1] * c1v.y
            + wo[q4 * 4 + 2] * c1v.z + wo[q4 * 4 + 3] * c1v.w;
    }
    float* Mout = g_M + (size_t)b * HIDDEN * HIDDEN + o * HIDDEN;
    Mout[col0]     = s0 * sinv[col0];
    Mout[col0 + 1] = s1 * sinv[col0 + 1];
}

// ---------------- K4: bf16 mma y = M_b @ softq + bo, + stats ----------------
// grid (32 ncol, 32 b), 256 threads, double-buffered
__global__ void __launch_bounds__(256) k4_out(const float* __restrict__ bo)
{
    __shared__ uint32_t sA[2 * SLAB_U32];
    __shared__ uint32_t sB[2 * SLAB_U32];
    __shared__ float redS[8], redQ[8];

    const int b  = blockIdx.y;
    const int n0 = blockIdx.x * 128;
    const int tid = threadIdx.x;
    const int lane = tid & 31, wid = tid >> 5;
    const int mbase = (wid >> 2) * 64, nbase = (wid & 3) * 32;
    const int gid = lane >> 2, tig = lane & 3;

    const float* Mb = g_M + (size_t)b * HIDDEN * HIDDEN;
    const float* qb = g_qkv + (size_t)b * 384 * NN + n0;

    const int arow = tid & 127, ah = tid >> 7;
    const int pk = tid >> 5, bn = (tid & 31) * 4;

    Frag f;
#pragma unroll
    for (int mt = 0; mt < 4; mt++)
#pragma unroll
        for (int nt = 0; nt < 4; nt++)
#pragma unroll
            for (int r = 0; r < 4; r++) f.d[mt][nt][r] = 0.f;

    float4 w0 = *(const float4*)&Mb[arow * 128 + ah * 8];
    float4 w1 = *(const float4*)&Mb[arow * 128 + ah * 8 + 4];
    float4 x0 = *(const float4*)&qb[(size_t)(2 * pk) * NN + bn];
    float4 x1 = *(const float4*)&qb[(size_t)(2 * pk + 1) * NN + bn];
    stage_A(sA, arow, ah, w0, w1);
    {
        uint4 p;
        p.x = pack_bf16(x0.x, x1.x); p.y = pack_bf16(x0.y, x1.y);
        p.z = pack_bf16(x0.z, x1.z); p.w = pack_bf16(x0.w, x1.w);
        *(uint4*)&sB[pk * PSTRIDE + bn] = p;
    }
    __syncthreads();

    for (int kt = 0; kt < 8; kt++) {
        const int cur = kt & 1;
        if (kt < 7) {
            const int k0 = (kt + 1) * 16;
            w0 = *(const float4*)&Mb[arow * 128 + k0 + ah * 8];
            w1 = *(const float4*)&Mb[arow * 128 + k0 + ah * 8 + 4];
            x0 = *(const float4*)&qb[(size_t)(k0 + 2 * pk) * NN + bn];
            x1 = *(const float4*)&qb[(size_t)(k0 + 2 * pk + 1) * NN + bn];
        }
        slab_mma(f, sA + cur * SLAB_U32, sB + cur * SLAB_U32, mbase, nbase, gid, tig);
        if (kt < 7) {
            stage_A(sA + (1 - cur) * SLAB_U32, arow, ah, w0, w1);
            uint4 p;
            p.x = pack_bf16(x0.x, x1.x); p.y = pack_bf16(x0.y, x1.y);
            p.z = pack_bf16(x0.z, x1.z); p.w = pack_bf16(x0.w, x1.w);
            *(uint4*)&sB[(1 - cur) * SLAB_U32 + pk * PSTRIDE + bn] = p;
            __syncthreads();
        }
    }

    float* outp = g_y + (size_t)b * C * NN + n0;
    float lsum = 0.f, lsq = 0.f;
#pragma unroll
    for (int mt = 0; mt < 4; mt++) {
        int row = mbase + mt * 16 + gid;
        float bb0 = bo[row], bb8 = bo[row + 8];
#pragma unroll
        for (int nt = 0; nt < 4; nt++) {
            int col = nbase + nt * 8 + tig * 2;
            float v0 = f.d[mt][nt][0] + bb0, v1 = f.d[mt][nt][1] + bb0;
            float v2 = f.d[mt][nt][2] + bb8, v3 = f.d[mt][nt][3] + bb8;
            *(float2*)&outp[(size_t)row * NN + col] = make_float2(v0, v1);
            *(float2*)&outp[(size_t)(row + 8) * NN + col] = make_float2(v2, v3);
            lsum += v0 + v1 + v2 + v3;
            lsq  += v0 * v0 + v1 * v1 + v2 * v2 + v3 * v3;
        }
    }
    const int w = tid >> 5;
#pragma unroll
    for (int o = 16; o; o >>= 1) {
        lsum += __shfl_xor_sync(0xffffffffu, lsum, o);
        lsq  += __shfl_xor_sync(0xffffffffu, lsq,  o);
    }
    if (lane == 0) { redS[w] = lsum; redQ[w] = lsq; }
    __syncthreads();
    if (tid == 0) {
        float s = 0.f, q = 0.f;
#pragma unroll
        for (int i = 0; i < 8; i++) { s += redS[i]; q += redQ[i]; }
        atomicAdd(&g_sum[b], s);
        atomicAdd(&g_sumsq[b], q);
    }
}

// ---------------- K5: GroupNorm, float4 ----------------
__global__ void __launch_bounds__(256) k5_norm(
    const float* __restrict__ gn_w, const float* __restrict__ gn_b,
    float* __restrict__ out)
{
    int i4 = blockIdx.x * 256 + threadIdx.x;
    int b = i4 >> 17;
    int c = (i4 >> 10) & 127;
    const float cn = (float)(C * NN);
    float mu = g_sum[b] / cn;
    float var = g_sumsq[b] / cn - mu * mu;
    float is = rsqrtf(var + GEPS);
    float w = gn_w[c] * is, bb = gn_b[c] - mu * w;
    float4 v = *(const float4*)&g_y[(size_t)i4 * 4];
    v.x = v.x * w + bb; v.y = v.y * w + bb;
    v.z = v.z * w + bb; v.w = v.w * w + bb;
    *(float4*)&out[(size_t)i4 * 4] = v;
}

// ---------------- launch ----------------
extern "C" void kernel_launch(void* const* d_in, const int* in_sizes, int n_in,
                              void* d_out, int out_size)
{
    const float* x  = (const float*)d_in[0];
    const float* Wq = (const float*)d_in[1];
    const float* Wk = (const float*)d_in[2];
    const float* Wv = (const float*)d_in[3];
    const float* Wo = (const float*)d_in[4];
    const float* bo = (const float*)d_in[5];
    const float* gw = (const float*)d_in[6];
    const float* gb = (const float*)d_in[7];
    float* out = (float*)d_out;

    static int smem_set = 0;
    const int K1_SMEM = 128 * 132 * 4;   // 67584 B; mainloop needs (2*SLAB+X)*4 = 43520 B
    if (!smem_set) {
        cudaFuncSetAttribute(k1_fused, cudaFuncAttributeMaxDynamicSharedMemorySize, K1_SMEM);
        smem_set = 1;
    }

    k0_zero<<<132, 256>>>();
    k1_fused<<<dim3(32, 32), 256, K1_SMEM>>>(x, Wq, Wk, Wv);
    k2_ctx<<<dim3(8, 128), 256>>>();
    k3_fold<<<dim3(32, 32), 256>>>(Wo);
    k4_out<<<dim3(32, 32), 256>>>(bo);
    k5_norm<<<16384, 256>>>(gw, gb, out);
}

// round 9
// speedup vs baseline: 1.7744x; 1.4355x over previous
#include <cuda_runtime.h>
#include <cstdint>
#include <math.h>

#define B 32
#define C 128
#define NN 4096
#define HEADS 4
#define DH 32
#define HIDDEN 128
#define QSCALE 0.17677669529663687f   /* 32^-0.5 */
#define GEPS 1e-5f

// ---------------- scratch ----------------
__device__ float g_qkv[(size_t)B * 384 * NN];      // 128-255 k, 256-383 v (q region unused)
__device__ uint32_t g_qbf[(size_t)B * 64 * NN];    // softmaxed q, bf16x2 pairs [pair][n]
__device__ uint32_t g_Mbf[B * 64 * HIDDEN];        // folded M, bf16x2 pairs [pair][row]
__device__ float g_ctx[B * HEADS * DH * DH];       // unnormalized ctx partials
__device__ float g_rsum[B * HIDDEN];               // per (b, row) sum of exp(k)
__device__ float g_y[(size_t)B * C * NN];
__device__ float g_sum[B];
__device__ float g_sumsq[B];

__device__ __forceinline__ uint32_t pack_bf16(float lo, float hi) {
    uint32_t r;
    asm("cvt.rn.bf16x2.f32 %0, %1, %2;" : "=r"(r) : "f"(hi), "f"(lo));
    return r;
}

__device__ __forceinline__ void mma_bf16(float* d, const uint32_t* a, const uint32_t* b) {
    asm("mma.sync.aligned.m16n8k16.row.col.f32.bf16.bf16.f32 "
        "{%0,%1,%2,%3}, {%4,%5,%6,%7}, {%8,%9}, {%0,%1,%2,%3};"
        : "+f"(d[0]), "+f"(d[1]), "+f"(d[2]), "+f"(d[3])
        : "r"(a[0]), "r"(a[1]), "r"(a[2]), "r"(a[3]), "r"(b[0]), "r"(b[1]));
}

// ---------------- K0: zero accumulators ----------------
__global__ void __launch_bounds__(256) k0_zero() {
    int gid = blockIdx.x * 256 + threadIdx.x;
    float4 z = make_float4(0.f, 0.f, 0.f, 0.f);
    if (gid < 32768) ((float4*)g_ctx)[gid] = z;
    if (gid < 1024)  ((float4*)g_rsum)[gid] = z;
    if (gid < 32) { g_sum[gid] = 0.f; g_sumsq[gid] = 0.f; }
}

// ---------------- bf16 mma helpers (k1/k4) ----------------
#define PSTRIDE 136
#define SLAB_U32 (8 * PSTRIDE)
#define X_U32    (64 * PSTRIDE)

struct Frag { float d[4][4][4]; };

__device__ __forceinline__ void stage_A(
    uint32_t* sA, int arow, int ah, const float4& w0, const float4& w1)
{
    sA[(ah * 4 + 0) * PSTRIDE + arow] = pack_bf16(w0.x, w0.y);
    sA[(ah * 4 + 1) * PSTRIDE + arow] = pack_bf16(w0.z, w0.w);
    sA[(ah * 4 + 2) * PSTRIDE + arow] = pack_bf16(w1.x, w1.y);
    sA[(ah * 4 + 3) * PSTRIDE + arow] = pack_bf16(w1.z, w1.w);
}

__device__ __forceinline__ void slab_mma(
    Frag& f, const uint32_t* sA, const uint32_t* sB,
    int mbase, int nbase, int gid, int tig)
{
    uint32_t a[4][4], bf[4][2];
#pragma unroll
    for (int mt = 0; mt < 4; mt++) {
        int row = mbase + mt * 16 + gid;
        a[mt][0] = sA[tig * PSTRIDE + row];
        a[mt][1] = sA[tig * PSTRIDE + row + 8];
        a[mt][2] = sA[(tig + 4) * PSTRIDE + row];
        a[mt][3] = sA[(tig + 4) * PSTRIDE + row + 8];
    }
#pragma unroll
    for (int nt = 0; nt < 4; nt++) {
        int col = nbase + nt * 8 + gid;
        bf[nt][0] = sB[tig * PSTRIDE + col];
        bf[nt][1] = sB[(tig + 4) * PSTRIDE + col];
    }
#pragma unroll
    for (int mt = 0; mt < 4; mt++)
#pragma unroll
        for (int nt = 0; nt < 4; nt++)
            mma_bf16(f.d[mt][nt], a[mt], bf[nt]);
}

// ---------------- K1: fused qkv projection, x staged once ----------------
// grid (32 ncol, 32 b), 256 threads; rt order k, v, q (q last, packed bf16 out)
__global__ void __launch_bounds__(256) k1_fused(
    const float* __restrict__ x,
    const float* __restrict__ Wq,
    const float* __restrict__ Wk,
    const float* __restrict__ Wv)
{
    extern __shared__ uint32_t dsm[];
    uint32_t* sA = dsm;
    uint32_t* sX = dsm + 2 * SLAB_U32;
    float* stage = (float*)dsm;   // aliased [128][132] for q epilogue

    const int b  = blockIdx.y;
    const int n0 = blockIdx.x * 128;
    const int tid = threadIdx.x;
    const int lane = tid & 31, wid = tid >> 5;
    const int mbase = (wid >> 2) * 64, nbase = (wid & 3) * 32;
    const int gid = lane >> 2, tig = lane & 3;

    const float* xb = x + (size_t)b * C * NN + n0;
    const int arow = tid & 127, ah = tid >> 7;

    // stage full x tile as bf16 pairs
    {
        const int colg = (tid & 31) * 4;
        const int pr0 = tid >> 5;
#pragma unroll
        for (int i = 0; i < 8; i++) {
            int pair = i * 8 + pr0;
            float4 x0 = *(const float4*)&xb[(size_t)(2 * pair) * NN + colg];
            float4 x1 = *(const float4*)&xb[(size_t)(2 * pair + 1) * NN + colg];
            uint4 p;
            p.x = pack_bf16(x0.x, x1.x);
            p.y = pack_bf16(x0.y, x1.y);
            p.z = pack_bf16(x0.z, x1.z);
            p.w = pack_bf16(x0.w, x1.w);
            *(uint4*)&sX[pair * PSTRIDE + colg] = p;
        }
    }
    __syncthreads();

#pragma unroll 1
    for (int rti = 0; rti < 3; rti++) {
        const int rt = (rti + 1) % 3;   // 1 (k), 2 (v), 0 (q last)
        const float* Wp = (rt == 0) ? Wq : ((rt == 1) ? Wk : Wv);

        Frag f;
#pragma unroll
        for (int mt = 0; mt < 4; mt++)
#pragma unroll
            for (int nt = 0; nt < 4; nt++)
#pragma unroll
                for (int r = 0; r < 4; r++) f.d[mt][nt][r] = 0.f;

        float4 w0 = *(const float4*)&Wp[arow * 128 + ah * 8];
        float4 w1 = *(const float4*)&Wp[arow * 128 + ah * 8 + 4];
        stage_A(sA, arow, ah, w0, w1);
        __syncthreads();

        for (int kt = 0; kt < 8; kt++) {
            const int cur = kt & 1;
            if (kt < 7) {
                const int k0 = (kt + 1) * 16;
                w0 = *(const float4*)&Wp[arow * 128 + k0 + ah * 8];
                w1 = *(const float4*)&Wp[arow * 128 + k0 + ah * 8 + 4];
            }
            slab_mma(f, sA + cur * SLAB_U32, sX + kt * SLAB_U32, mbase, nbase, gid, tig);
            if (kt < 7) {
                stage_A(sA + (1 - cur) * SLAB_U32, arow, ah, w0, w1);
                __syncthreads();
            }
        }

        if (rt != 0) {
            float* outp = g_qkv + ((size_t)b * 384 + rt * 128) * NN + n0;
#pragma unroll
            for (int mt = 0; mt < 4; mt++) {
#pragma unroll
                for (int nt = 0; nt < 4; nt++) {
                    int row = mbase + mt * 16 + gid;
                    int col = nbase + nt * 8 + tig * 2;
                    *(float2*)&outp[(size_t)row * NN + col] =
                        make_float2(f.d[mt][nt][0], f.d[mt][nt][1]);
                    *(float2*)&outp[(size_t)(row + 8) * NN + col] =
                        make_float2(f.d[mt][nt][2], f.d[mt][nt][3]);
                }
            }
            __syncthreads();
            continue;
        }

        // q: stage -> softmax over d -> packed bf16x2 write
        __syncthreads();
#pragma unroll
        for (int mt = 0; mt < 4; mt++) {
#pragma unroll
            for (int nt = 0; nt < 4; nt++) {
                int row = mbase + mt * 16 + gid;
                int col = nbase + nt * 8 + tig * 2;
                *(float2*)&stage[row * 132 + col] =
                    make_float2(f.d[mt][nt][0], f.d[mt][nt][1]);
                *(float2*)&stage[(row + 8) * 132 + col] =
                    make_float2(f.d[mt][nt][2], f.d[mt][nt][3]);
            }
        }
        __syncthreads();

        uint32_t* outq = g_qbf + (size_t)b * 64 * NN + n0;
#pragma unroll
        for (int t = tid; t < 512; t += 256) {
            const int col = t & 127;
            const int h = t >> 7;
            float sum = 0.f;
#pragma unroll
            for (int dd = 0; dd < 32; dd++) {
                float* p = &stage[(h * 32 + dd) * 132 + col];
                float e = __expf(*p);
                *p = e;
                sum += e;
            }
            float inv = QSCALE / sum;
#pragma unroll
            for (int dp = 0; dp < 16; dp++) {
                float lo = stage[(h * 32 + 2 * dp) * 132 + col] * inv;
                float hi = stage[(h * 32 + 2 * dp + 1) * 132 + col] * inv;
                outq[(size_t)(h * 16 + dp) * NN + col] = pack_bf16(lo, hi);
            }
        }
    }
}

// ---------------- K2: bf16 mma partial ctx = exp(k) @ v^T + rowsum ----------------
// grid (8 chunks, 128 bh), 256 threads (8 warps); chunk = 512 n, 2 halves of 256
#define K2PAD 34
#define K2HALF (128 * K2PAD)   /* 4352 u32 per matrix per half */
__global__ void __launch_bounds__(256) k2_ctx()
{
    __shared__ uint32_t s2[2 * K2HALF];   // sKb | sVb; aliased as partials later
    uint32_t* sKb = s2;
    uint32_t* sVb = s2 + K2HALF;

    const int bh = blockIdx.y;
    const int b = bh >> 2, h = bh & 3;
    const int cbase = blockIdx.x * 512;
    const float* kb = g_qkv + ((size_t)b * 384 + 128 + h * 32) * NN + cbase;
    const float* vb = g_qkv + ((size_t)b * 384 + 256 + h * 32) * NN + cbase;

    const int tid = threadIdx.x;
    const int lane = tid & 31, w = tid >> 5;
    const int gid = lane >> 2, tig = lane & 3;

    const int row = tid >> 3;            // loader row 0..31
    const int cg  = (tid & 7) * 4;       // loader col base (stride 32 per j)

    float c[2][4][4];
#pragma unroll
    for (int mt = 0; mt < 2; mt++)
#pragma unroll
        for (int nt = 0; nt < 4; nt++)
#pragma unroll
            for (int r = 0; r < 4; r++) c[mt][nt][r] = 0.f;
    float lsum = 0.f;

#pragma unroll 1
    for (int half = 0; half < 2; half++) {
        const int noff = half * 256;
        __syncthreads();
        // stage exp(k) and v as bf16 pairs: s[pair][row], pad K2PAD
#pragma unroll
        for (int j = 0; j < 8; j++) {
            int cc = cg + 32 * j;
            float4 t = *(const float4*)&kb[(size_t)row * NN + noff + cc];
            float e0 = __expf(t.x), e1 = __expf(t.y);
            float e2 = __expf(t.z), e3 = __expf(t.w);
            lsum += e0 + e1 + e2 + e3;
            int npair = cc >> 1;
            sKb[npair * K2PAD + row] = pack_bf16(e0, e1);
            sKb[(npair + 1) * K2PAD + row] = pack_bf16(e2, e3);
            float4 v = *(const float4*)&vb[(size_t)row * NN + noff + cc];
            sVb[npair * K2PAD + row] = pack_bf16(v.x, v.y);
            sVb[(npair + 1) * K2PAD + row] = pack_bf16(v.z, v.w);
        }
        __syncthreads();
        // warp w covers n slice [w*32, w*32+32) of this half -> pairs w*16..+15
#pragma unroll
        for (int kt = 0; kt < 2; kt++) {
            const int base = w * 16 + kt * 8;
            uint32_t a[2][4], bf[4][2];
#pragma unroll
            for (int mt = 0; mt < 2; mt++) {
                int r2 = mt * 16 + gid;
                a[mt][0] = sKb[(base + tig) * K2PAD + r2];
                a[mt][1] = sKb[(base + tig) * K2PAD + r2 + 8];
                a[mt][2] = sKb[(base + tig + 4) * K2PAD + r2];
                a[mt][3] = sKb[(base + tig + 4) * K2PAD + r2 + 8];
            }
#pragma unroll
            for (int nt = 0; nt < 4; nt++) {
                int col = nt * 8 + gid;
                bf[nt][0] = sVb[(base + tig) * K2PAD + col];
                bf[nt][1] = sVb[(base + tig + 4) * K2PAD + col];
            }
#pragma unroll
            for (int mt = 0; mt < 2; mt++)
#pragma unroll
                for (int nt = 0; nt < 4; nt++)
                    mma_bf16(c[mt][nt], a[mt], bf[nt]);
        }
    }

    // rowsum reduce across the 8 threads sharing a row
#pragma unroll
    for (int o = 4; o; o >>= 1) lsum += __shfl_xor_sync(0xffffffffu, lsum, o);
    if ((tid & 7) == 0)
        atomicAdd(&g_rsum[b * HIDDEN + h * 32 + row], lsum);

    // warp partials -> smem (aliases staging), then cross-warp reduce + atomic
    __syncthreads();
    float* pb = (float*)s2;   // [8 warps][32 rows][K2PAD]
#pragma unroll
    for (int mt = 0; mt < 2; mt++) {
#pragma unroll
        for (int nt = 0; nt < 4; nt++) {
            int r2 = mt * 16 + gid;
            int col = nt * 8 + tig * 2;
            pb[(w * 32 + r2) * K2PAD + col]     = c[mt][nt][0];
            pb[(w * 32 + r2) * K2PAD + col + 1] = c[mt][nt][1];
            pb[(w * 32 + r2 + 8) * K2PAD + col]     = c[mt][nt][2];
            pb[(w * 32 + r2 + 8) * K2PAD + col + 1] = c[mt][nt][3];
        }
    }
    __syncthreads();
    {
        const int d = tid >> 3;
        const int e0 = (tid & 7) * 4;
        float s0 = 0.f, s1 = 0.f, s2v = 0.f, s3 = 0.f;
#pragma unroll
        for (int ww = 0; ww < 8; ww++) {
            const float* p = &pb[(ww * 32 + d) * K2PAD + e0];
            s0 += p[0]; s1 += p[1]; s2v += p[2]; s3 += p[3];
        }
        float* cp = &g_ctx[((size_t)bh * 32 + d) * 32 + e0];
        atomicAdd(cp + 0, s0);
        atomicAdd(cp + 1, s1);
        atomicAdd(cp + 2, s2v);
        atomicAdd(cp + 3, s3);
    }
}

// ---------------- K3: M_b = Wo @ blockdiag(ctx^T / rsum), packed bf16 out ----------------
__global__ void __launch_bounds__(256) k3_fold(const float* __restrict__ Wo)
{
    const int b = blockIdx.y;
    const int og = blockIdx.x * 4;
    __shared__ float sctx[HEADS * DH * DH];
    __shared__ float sinv[HIDDEN];
    const int tid = threadIdx.x;
#pragma unroll
    for (int rr = 0; rr < 4; rr++) {
        int idx = tid + rr * 256;
        *(float4*)&sctx[idx * 4] = *(const float4*)&g_ctx[(size_t)b * 4096 + idx * 4];
    }
    if (tid < 128) sinv[tid] = 1.0f / g_rsum[b * HIDDEN + tid];
    __syncthreads();

    const int o = og + (tid >> 6);
    const int col0 = (tid & 63) * 2;
    const int h = col0 >> 5;
    const int d0 = col0 & 31;

    float wo[32];
#pragma unroll
    for (int q4 = 0; q4 < 8; q4++) {
        float4 t = *(const float4*)&Wo[o * 128 + h * 32 + q4 * 4];
        wo[q4 * 4 + 0] = t.x; wo[q4 * 4 + 1] = t.y;
        wo[q4 * 4 + 2] = t.z; wo[q4 * 4 + 3] = t.w;
    }
    float s0 = 0.f, s1 = 0.f;
#pragma unroll
    for (int q4 = 0; q4 < 8; q4++) {
        float4 c0v = *(const float4*)&sctx[(h * 32 + d0) * 32 + q4 * 4];
        float4 c1v = *(const float4*)&sctx[(h * 32 + d0 + 1) * 32 + q4 * 4];
        s0 += wo[q4 * 4 + 0] * c0v.x + wo[q4 * 4 + 1] * c0v.y
            + wo[q4 * 4 + 2] * c0v.z + wo[q4 * 4 + 3] * c0v.w;
        s1 += wo[q4 * 4 + 0] * c1v.x + wo[q4 * 4 + 1] * c1v.y
            + wo[q4 * 4 + 2] * c1v.z + wo[q4 * 4 + 3] * c1v.w;
    }
    g_Mbf[b * 8192 + (col0 >> 1) * 128 + o] =
        pack_bf16(s0 * sinv[col0], s1 * sinv[col0 + 1]);
}

// ---------------- K4: bf16 mma y = M_b @ softq + bo, prepacked operands ----------------
// grid (32 ncol, 32 b), 256 threads, double-buffered
__global__ void __launch_bounds__(256) k4_out(const float* __restrict__ bo)
{
    __shared__ uint32_t sA[2 * SLAB_U32];
    __shared__ uint32_t sB[2 * SLAB_U32];
    __shared__ float redS[8], redQ[8];

    const int b  = blockIdx.y;
    const int n0 = blockIdx.x * 128;
    const int tid = threadIdx.x;
    const int lane = tid & 31, wid = tid >> 5;
    const int mbase = (wid >> 2) * 64, nbase = (wid & 3) * 32;
    const int gid = lane >> 2, tig = lane & 3;

    const uint32_t* Mb = g_Mbf + b * 8192;                 // [64 pair][128 row]
    const uint32_t* qb = g_qbf + (size_t)b * 64 * NN + n0; // [64 pair][4096 n]

    const int pr = tid >> 5;            // pair within slab (0..7)
    const int r4 = (tid & 31) * 4;      // 4 rows / 4 cols

    Frag f;
#pragma unroll
    for (int mt = 0; mt < 4; mt++)
#pragma unroll
        for (int nt = 0; nt < 4; nt++)
#pragma unroll
            for (int r = 0; r < 4; r++) f.d[mt][nt][r] = 0.f;

    uint4 wv = *(const uint4*)&Mb[pr * 128 + r4];
    uint4 xv = *(const uint4*)&qb[(size_t)pr * NN + r4];
    *(uint4*)&sA[pr * PSTRIDE + r4] = wv;
    *(uint4*)&sB[pr * PSTRIDE + r4] = xv;
    __syncthreads();

    for (int kt = 0; kt < 8; kt++) {
        const int cur = kt & 1;
        if (kt < 7) {
            const int p0 = (kt + 1) * 8 + pr;
            wv = *(const uint4*)&Mb[p0 * 128 + r4];
            xv = *(const uint4*)&qb[(size_t)p0 * NN + r4];
        }
        slab_mma(f, sA + cur * SLAB_U32, sB + cur * SLAB_U32, mbase, nbase, gid, tig);
        if (kt < 7) {
            *(uint4*)&sA[(1 - cur) * SLAB_U32 + pr * PSTRIDE + r4] = wv;
            *(uint4*)&sB[(1 - cur) * SLAB_U32 + pr * PSTRIDE + r4] = xv;
            __syncthreads();
        }
    }

    float* outp = g_y + (size_t)b * C * NN + n0;
    float lsum = 0.f, lsq = 0.f;
#pragma unroll
    for (int mt = 0; mt < 4; mt++) {
        int row = mbase + mt * 16 + gid;
        float bb0 = bo[row], bb8 = bo[row + 8];
#pragma unroll
        for (int nt = 0; nt < 4; nt++) {
            int col = nbase + nt * 8 + tig * 2;
            float v0 = f.d[mt][nt][0] + bb0, v1 = f.d[mt][nt][1] + bb0;
            float v2 = f.d[mt][nt][2] + bb8, v3 = f.d[mt][nt][3] + bb8;
            *(float2*)&outp[(size_t)row * NN + col] = make_float2(v0, v1);
            *(float2*)&outp[(size_t)(row + 8) * NN + col] = make_float2(v2, v3);
            lsum += v0 + v1 + v2 + v3;
            lsq  += v0 * v0 + v1 * v1 + v2 * v2 + v3 * v3;
        }
    }
#pragma unroll
    for (int o = 16; o; o >>= 1) {
        lsum += __shfl_xor_sync(0xffffffffu, lsum, o);
        lsq  += __shfl_xor_sync(0xffffffffu, lsq,  o);
    }
    if (lane == 0) { redS[wid] = lsum; redQ[wid] = lsq; }
    __syncthreads();
    if (tid == 0) {
        float s = 0.f, q = 0.f;
#pragma unroll
        for (int i = 0; i < 8; i++) { s += redS[i]; q += redQ[i]; }
        atomicAdd(&g_sum[b], s);
        atomicAdd(&g_sumsq[b], q);
    }
}

// ---------------- K5: GroupNorm, float4 ----------------
__global__ void __launch_bounds__(256) k5_norm(
    const float* __restrict__ gn_w, const float* __restrict__ gn_b,
    float* __restrict__ out)
{
    int i4 = blockIdx.x * 256 + threadIdx.x;
    int b = i4 >> 17;
    int c = (i4 >> 10) & 127;
    const float cn = (float)(C * NN);
    float mu = g_sum[b] / cn;
    float var = g_sumsq[b] / cn - mu * mu;
    float is = rsqrtf(var + GEPS);
    float w = gn_w[c] * is, bb = gn_b[c] - mu * w;
    float4 v = *(const float4*)&g_y[(size_t)i4 * 4];
    v.x = v.x * w + bb; v.y = v.y * w + bb;
    v.z = v.z * w + bb; v.w = v.w * w + bb;
    *(float4*)&out[(size_t)i4 * 4] = v;
}

// ---------------- launch ----------------
extern "C" void kernel_launch(void* const* d_in, const int* in_sizes, int n_in,
                              void* d_out, int out_size)
{
    const float* x  = (const float*)d_in[0];
    const float* Wq = (const float*)d_in[1];
    const float* Wk = (const float*)d_in[2];
    const float* Wv = (const float*)d_in[3];
    const float* Wo = (const float*)d_in[4];
    const float* bo = (const float*)d_in[5];
    const float* gw = (const float*)d_in[6];
    const float* gb = (const float*)d_in[7];
    float* out = (float*)d_out;

    static int smem_set = 0;
    const int K1_SMEM = 128 * 132 * 4;   // 67584 B
    if (!smem_set) {
        cudaFuncSetAttribute(k1_fused, cudaFuncAttributeMaxDynamicSharedMemorySize, K1_SMEM);
        smem_set = 1;
    }

    k0_zero<<<132, 256>>>();
    k1_fused<<<dim3(32, 32), 256, K1_SMEM>>>(x, Wq, Wk, Wv);
    k2_ctx<<<dim3(8, 128), 256>>>();
    k3_fold<<<dim3(32, 32), 256>>>(Wo);
    k4_out<<<dim3(32, 32), 256>>>(bo);
    k5_norm<<<16384, 256>>>(gw, gb, out);
}

// round 10
// speedup vs baseline: 1.8849x; 1.0623x over previous
#include <cuda_runtime.h>
#include <cstdint>
#include <math.h>

#define B 32
#define C 128
#define NN 4096
#define HEADS 4
#define DH 32
#define HIDDEN 128
#define QSCALE 0.17677669529663687f   /* 32^-0.5 */
#define GEPS 1e-5f

// ---------------- scratch ----------------
__device__ uint32_t g_kv[(size_t)B * 2 * 128 * 2048];  // k/v packed bf16x2 [b][kv][row][npair]
__device__ uint32_t g_qbf[(size_t)B * 64 * NN];        // softmaxed q, bf16x2 pairs [pair][n]
__device__ uint32_t g_Mbf[B * 64 * HIDDEN];            // folded M, bf16x2 pairs [pair][row]
__device__ float g_ctx[B * HEADS * DH * DH];           // unnormalized ctx partials
__device__ float g_rsum[B * HIDDEN];                   // per (b, row) sum of exp(k)
__device__ float g_y[(size_t)B * C * NN];
__device__ float g_sum[B];
__device__ float g_sumsq[B];

__device__ __forceinline__ uint32_t pack_bf16(float lo, float hi) {
    uint32_t r;
    asm("cvt.rn.bf16x2.f32 %0, %1, %2;" : "=r"(r) : "f"(hi), "f"(lo));
    return r;
}

__device__ __forceinline__ void mma_bf16(float* d, const uint32_t* a, const uint32_t* b) {
    asm("mma.sync.aligned.m16n8k16.row.col.f32.bf16.bf16.f32 "
        "{%0,%1,%2,%3}, {%4,%5,%6,%7}, {%8,%9}, {%0,%1,%2,%3};"
        : "+f"(d[0]), "+f"(d[1]), "+f"(d[2]), "+f"(d[3])
        : "r"(a[0]), "r"(a[1]), "r"(a[2]), "r"(a[3]), "r"(b[0]), "r"(b[1]));
}

// ---------------- K0: zero accumulators ----------------
__global__ void __launch_bounds__(256) k0_zero() {
    int gid = blockIdx.x * 256 + threadIdx.x;
    float4 z = make_float4(0.f, 0.f, 0.f, 0.f);
    if (gid < 32768) ((float4*)g_ctx)[gid] = z;
    if (gid < 1024)  ((float4*)g_rsum)[gid] = z;
    if (gid < 32) { g_sum[gid] = 0.f; g_sumsq[gid] = 0.f; }
}

// ---------------- bf16 mma helpers (k1/k4) ----------------
#define PSTRIDE 136
#define SLAB_U32 (8 * PSTRIDE)

struct Frag { float d[4][4][4]; };

__device__ __forceinline__ void stage_A(
    uint32_t* sA, int arow, int ah, const float4& w0, const float4& w1)
{
    sA[(ah * 4 + 0) * PSTRIDE + arow] = pack_bf16(w0.x, w0.y);
    sA[(ah * 4 + 1) * PSTRIDE + arow] = pack_bf16(w0.z, w0.w);
    sA[(ah * 4 + 2) * PSTRIDE + arow] = pack_bf16(w1.x, w1.y);
    sA[(ah * 4 + 3) * PSTRIDE + arow] = pack_bf16(w1.z, w1.w);
}

__device__ __forceinline__ void slab_mma(
    Frag& f, const uint32_t* sA, const uint32_t* sB,
    int mbase, int nbase, int gid, int tig)
{
    uint32_t a[4][4], bf[4][2];
#pragma unroll
    for (int mt = 0; mt < 4; mt++) {
        int row = mbase + mt * 16 + gid;
        a[mt][0] = sA[tig * PSTRIDE + row];
        a[mt][1] = sA[tig * PSTRIDE + row + 8];
        a[mt][2] = sA[(tig + 4) * PSTRIDE + row];
        a[mt][3] = sA[(tig + 4) * PSTRIDE + row + 8];
    }
#pragma unroll
    for (int nt = 0; nt < 4; nt++) {
        int col = nbase + nt * 8 + gid;
        bf[nt][0] = sB[tig * PSTRIDE + col];
        bf[nt][1] = sB[(tig + 4) * PSTRIDE + col];
    }
#pragma unroll
    for (int mt = 0; mt < 4; mt++)
#pragma unroll
        for (int nt = 0; nt < 4; nt++)
            mma_bf16(f.d[mt][nt], a[mt], bf[nt]);
}

// ---------------- K1: fused qkv projection, x staged once ----------------
// grid (32 ncol, 32 b), 256 threads; rt order k, v, q (q last)
__global__ void __launch_bounds__(256) k1_fused(
    const float* __restrict__ x,
    const float* __restrict__ Wq,
    const float* __restrict__ Wk,
    const float* __restrict__ Wv)
{
    extern __shared__ uint32_t dsm[];
    uint32_t* sA = dsm;
    uint32_t* sX = dsm + 2 * SLAB_U32;
    float* stage = (float*)dsm;   // aliased [128][132] for q epilogue

    const int b  = blockIdx.y;
    const int n0 = blockIdx.x * 128;
    const int tid = threadIdx.x;
    const int lane = tid & 31, wid = tid >> 5;
    const int mbase = (wid >> 2) * 64, nbase = (wid & 3) * 32;
    const int gid = lane >> 2, tig = lane & 3;

    const float* xb = x + (size_t)b * C * NN + n0;
    const int arow = tid & 127, ah = tid >> 7;

    // stage full x tile as bf16 pairs
    {
        const int colg = (tid & 31) * 4;
        const int pr0 = tid >> 5;
#pragma unroll
        for (int i = 0; i < 8; i++) {
            int pair = i * 8 + pr0;
            float4 x0 = *(const float4*)&xb[(size_t)(2 * pair) * NN + colg];
            float4 x1 = *(const float4*)&xb[(size_t)(2 * pair + 1) * NN + colg];
            uint4 p;
            p.x = pack_bf16(x0.x, x1.x);
            p.y = pack_bf16(x0.y, x1.y);
            p.z = pack_bf16(x0.z, x1.z);
            p.w = pack_bf16(x0.w, x1.w);
            *(uint4*)&sX[pair * PSTRIDE + colg] = p;
        }
    }
    __syncthreads();

#pragma unroll 1
    for (int rti = 0; rti < 3; rti++) {
        const int rt = (rti + 1) % 3;   // 1 (k), 2 (v), 0 (q last)
        const float* Wp = (rt == 0) ? Wq : ((rt == 1) ? Wk : Wv);

        Frag f;
#pragma unroll
        for (int mt = 0; mt < 4; mt++)
#pragma unroll
            for (int nt = 0; nt < 4; nt++)
#pragma unroll
                for (int r = 0; r < 4; r++) f.d[mt][nt][r] = 0.f;

        float4 w0 = *(const float4*)&Wp[arow * 128 + ah * 8];
        float4 w1 = *(const float4*)&Wp[arow * 128 + ah * 8 + 4];
        stage_A(sA, arow, ah, w0, w1);
        __syncthreads();

        for (int kt = 0; kt < 8; kt++) {
            const int cur = kt & 1;
            if (kt < 7) {
                const int k0 = (kt + 1) * 16;
                w0 = *(const float4*)&Wp[arow * 128 + k0 + ah * 8];
                w1 = *(const float4*)&Wp[arow * 128 + k0 + ah * 8 + 4];
            }
            slab_mma(f, sA + cur * SLAB_U32, sX + kt * SLAB_U32, mbase, nbase, gid, tig);
            if (kt < 7) {
                stage_A(sA + (1 - cur) * SLAB_U32, arow, ah, w0, w1);
                __syncthreads();
            }
        }

        if (rt != 0) {
            // k/v: pack fragment col pairs -> bf16x2, write u32
            uint32_t* outp = g_kv + ((size_t)(b * 2 + (rt - 1)) * 128) * 2048 + (n0 >> 1);
#pragma unroll
            for (int mt = 0; mt < 4; mt++) {
#pragma unroll
                for (int nt = 0; nt < 4; nt++) {
                    int row = mbase + mt * 16 + gid;
                    int npair = ((nbase + nt * 8) >> 1) + tig;
                    outp[(size_t)row * 2048 + npair] =
                        pack_bf16(f.d[mt][nt][0], f.d[mt][nt][1]);
                    outp[(size_t)(row + 8) * 2048 + npair] =
                        pack_bf16(f.d[mt][nt][2], f.d[mt][nt][3]);
                }
            }
            __syncthreads();
            continue;
        }

        // q: stage -> softmax over d -> packed bf16x2 write
        __syncthreads();
#pragma unroll
        for (int mt = 0; mt < 4; mt++) {
#pragma unroll
            for (int nt = 0; nt < 4; nt++) {
                int row = mbase + mt * 16 + gid;
                int col = nbase + nt * 8 + tig * 2;
                *(float2*)&stage[row * 132 + col] =
                    make_float2(f.d[mt][nt][0], f.d[mt][nt][1]);
                *(float2*)&stage[(row + 8) * 132 + col] =
                    make_float2(f.d[mt][nt][2], f.d[mt][nt][3]);
            }
        }
        __syncthreads();

        uint32_t* outq = g_qbf + (size_t)b * 64 * NN + n0;
#pragma unroll
        for (int t = tid; t < 512; t += 256) {
            const int col = t & 127;
            const int h = t >> 7;
            float sum = 0.f;
#pragma unroll
            for (int dd = 0; dd < 32; dd++) {
                float* p = &stage[(h * 32 + dd) * 132 + col];
                float e = __expf(*p);
                *p = e;
                sum += e;
            }
            float inv = QSCALE / sum;
#pragma unroll
            for (int dp = 0; dp < 16; dp++) {
                float lo = stage[(h * 32 + 2 * dp) * 132 + col] * inv;
                float hi = stage[(h * 32 + 2 * dp + 1) * 132 + col] * inv;
                outq[(size_t)(h * 16 + dp) * NN + col] = pack_bf16(lo, hi);
            }
        }
    }
}

// ---------------- K2: bf16 mma partial ctx = exp(k) @ v^T + rowsum ----------------
// grid (8 chunks, 128 bh), 256 threads; chunk = 256 pairs, 2 halves of 128 pairs
#define K2PAD 34
#define K2HALF (128 * K2PAD)
__global__ void __launch_bounds__(256) k2_ctx()
{
    __shared__ uint32_t s2[2 * K2HALF];   // sKb | sVb; aliased as partials later
    uint32_t* sKb = s2;
    uint32_t* sVb = s2 + K2HALF;

    const int bh = blockIdx.y;
    const int b = bh >> 2, h = bh & 3;
    const int cbp = blockIdx.x * 256;    // chunk base in pairs
    const uint32_t* kb32 = g_kv + ((size_t)(b * 2 + 0) * 128 + h * 32) * 2048 + cbp;
    const uint32_t* vb32 = g_kv + ((size_t)(b * 2 + 1) * 128 + h * 32) * 2048 + cbp;

    const int tid = threadIdx.x;
    const int lane = tid & 31, w = tid >> 5;
    const int gid = lane >> 2, tig = lane & 3;

    const int row = tid >> 3;   // 0..31
    const int t   = tid & 7;

    float c[2][4][4];
#pragma unroll
    for (int mt = 0; mt < 2; mt++)
#pragma unroll
        for (int nt = 0; nt < 4; nt++)
#pragma unroll
            for (int r = 0; r < 4; r++) c[mt][nt][r] = 0.f;
    float lsum = 0.f;

#pragma unroll 1
    for (int half = 0; half < 2; half++) {
        const int pb = half * 128;
        __syncthreads();
#pragma unroll
        for (int j = 0; j < 8; j++) {
            int pr = 2 * t + 16 * j;
            uint2 kk = *(const uint2*)&kb32[(size_t)row * 2048 + pb + pr];
            float a0 = __uint_as_float(kk.x << 16);
            float a1 = __uint_as_float(kk.x & 0xffff0000u);
            float a2 = __uint_as_float(kk.y << 16);
            float a3 = __uint_as_float(kk.y & 0xffff0000u);
            float e0 = __expf(a0), e1 = __expf(a1);
            float e2 = __expf(a2), e3 = __expf(a3);
            lsum += e0 + e1 + e2 + e3;
            sKb[pr * K2PAD + row] = pack_bf16(e0, e1);
            sKb[(pr + 1) * K2PAD + row] = pack_bf16(e2, e3);
            uint2 vv = *(const uint2*)&vb32[(size_t)row * 2048 + pb + pr];
            sVb[pr * K2PAD + row] = vv.x;
            sVb[(pr + 1) * K2PAD + row] = vv.y;
        }
        __syncthreads();
#pragma unroll
        for (int kt = 0; kt < 2; kt++) {
            const int base = w * 16 + kt * 8;
            uint32_t a[2][4], bf[4][2];
#pragma unroll
            for (int mt = 0; mt < 2; mt++) {
                int r2 = mt * 16 + gid;
                a[mt][0] = sKb[(base + tig) * K2PAD + r2];
                a[mt][1] = sKb[(base + tig) * K2PAD + r2 + 8];
                a[mt][2] = sKb[(base + tig + 4) * K2PAD + r2];
                a[mt][3] = sKb[(base + tig + 4) * K2PAD + r2 + 8];
            }
#pragma unroll
            for (int nt = 0; nt < 4; nt++) {
                int col = nt * 8 + gid;
                bf[nt][0] = sVb[(base + tig) * K2PAD + col];
                bf[nt][1] = sVb[(base + tig + 4) * K2PAD + col];
            }
#pragma unroll
            for (int mt = 0; mt < 2; mt++)
#pragma unroll
                for (int nt = 0; nt < 4; nt++)
                    mma_bf16(c[mt][nt], a[mt], bf[nt]);
        }
    }

#pragma unroll
    for (int o = 4; o; o >>= 1) lsum += __shfl_xor_sync(0xffffffffu, lsum, o);
    if ((tid & 7) == 0)
        atomicAdd(&g_rsum[b * HIDDEN + h * 32 + row], lsum);

    __syncthreads();
    float* pbuf = (float*)s2;   // [8 warps][32 rows][K2PAD]
#pragma unroll
    for (int mt = 0; mt < 2; mt++) {
#pragma unroll
        for (int nt = 0; nt < 4; nt++) {
            int r2 = mt * 16 + gid;
            int col = nt * 8 + tig * 2;
            pbuf[(w * 32 + r2) * K2PAD + col]     = c[mt][nt][0];
            pbuf[(w * 32 + r2) * K2PAD + col + 1] = c[mt][nt][1];
            pbuf[(w * 32 + r2 + 8) * K2PAD + col]     = c[mt][nt][2];
            pbuf[(w * 32 + r2 + 8) * K2PAD + col + 1] = c[mt][nt][3];
        }
    }
    __syncthreads();
    {
        const int d = tid >> 3;
        const int e0 = (tid & 7) * 4;
        float s0 = 0.f, s1 = 0.f, s2v = 0.f, s3 = 0.f;
#pragma unroll
        for (int ww = 0; ww < 8; ww++) {
            const float* p = &pbuf[(ww * 32 + d) * K2PAD + e0];
            s0 += p[0]; s1 += p[1]; s2v += p[2]; s3 += p[3];
        }
        float* cp = &g_ctx[((size_t)bh * 32 + d) * 32 + e0];
        atomicAdd(cp + 0, s0);
        atomicAdd(cp + 1, s1);
        atomicAdd(cp + 2, s2v);
        atomicAdd(cp + 3, s3);
    }
}

// ---------------- K3: M_b = Wo @ blockdiag(ctx^T / rsum), packed bf16 out ----------------
__global__ void __launch_bounds__(256) k3_fold(const float* __restrict__ Wo)
{
    const int b = blockIdx.y;
    const int og = blockIdx.x * 4;
    __shared__ float sctx[HEADS * DH * DH];
    __shared__ float sinv[HIDDEN];
    const int tid = threadIdx.x;
#pragma unroll
    for (int rr = 0; rr < 4; rr++) {
        int idx = tid + rr * 256;
        *(float4*)&sctx[idx * 4] = *(const float4*)&g_ctx[(size_t)b * 4096 + idx * 4];
    }
    if (tid < 128) sinv[tid] = 1.0f / g_rsum[b * HIDDEN + tid];
    __syncthreads();

    const int o = og + (tid >> 6);
    const int col0 = (tid & 63) * 2;
    const int h = col0 >> 5;
    const int d0 = col0 & 31;

    float wo[32];
#pragma unroll
    for (int q4 = 0; q4 < 8; q4++) {
        float4 t = *(const float4*)&Wo[o * 128 + h * 32 + q4 * 4];
        wo[q4 * 4 + 0] = t.x; wo[q4 * 4 + 1] = t.y;
        wo[q4 * 4 + 2] = t.z; wo[q4 * 4 + 3] = t.w;
    }
    // 4 independent accumulation chains per output (ILP)
    float4 a0 = make_float4(0.f, 0.f, 0.f, 0.f);
    float4 a1 = make_float4(0.f, 0.f, 0.f, 0.f);
#pragma unroll
    for (int q4 = 0; q4 < 8; q4++) {
        float4 c0v = *(const float4*)&sctx[(h * 32 + d0) * 32 + q4 * 4];
        float4 c1v = *(const float4*)&sctx[(h * 32 + d0 + 1) * 32 + q4 * 4];
        a0.x += wo[q4 * 4 + 0] * c0v.x; a0.y += wo[q4 * 4 + 1] * c0v.y;
        a0.z += wo[q4 * 4 + 2] * c0v.z; a0.w += wo[q4 * 4 + 3] * c0v.w;
        a1.x += wo[q4 * 4 + 0] * c1v.x; a1.y += wo[q4 * 4 + 1] * c1v.y;
        a1.z += wo[q4 * 4 + 2] * c1v.z; a1.w += wo[q4 * 4 + 3] * c1v.w;
    }
    float s0 = (a0.x + a0.y) + (a0.z + a0.w);
    float s1 = (a1.x + a1.y) + (a1.z + a1.w);
    g_Mbf[b * 8192 + (col0 >> 1) * 128 + o] =
        pack_bf16(s0 * sinv[col0], s1 * sinv[col0 + 1]);
}

// ---------------- K4: bf16 mma y = M_b @ softq + bo, prepacked operands ----------------
__global__ void __launch_bounds__(256) k4_out(const float* __restrict__ bo)
{
    __shared__ uint32_t sA[2 * SLAB_U32];
    __shared__ uint32_t sB[2 * SLAB_U32];
    __shared__ float redS[8], redQ[8];

    const int b  = blockIdx.y;
    const int n0 = blockIdx.x * 128;
    const int tid = threadIdx.x;
    const int lane = tid & 31, wid = tid >> 5;
    const int mbase = (wid >> 2) * 64, nbase = (wid & 3) * 32;
    const int gid = lane >> 2, tig = lane & 3;

    const uint32_t* Mb = g_Mbf + b * 8192;
    const uint32_t* qb = g_qbf + (size_t)b * 64 * NN + n0;

    const int pr = tid >> 5;
    const int r4 = (tid & 31) * 4;

    Frag f;
#pragma unroll
    for (int mt = 0; mt < 4; mt++)
#pragma unroll
        for (int nt = 0; nt < 4; nt++)
#pragma unroll
            for (int r = 0; r < 4; r++) f.d[mt][nt][r] = 0.f;

    uint4 wv = *(const uint4*)&Mb[pr * 128 + r4];
    uint4 xv = *(const uint4*)&qb[(size_t)pr * NN + r4];
    *(uint4*)&sA[pr * PSTRIDE + r4] = wv;
    *(uint4*)&sB[pr * PSTRIDE + r4] = xv;
    __syncthreads();

    for (int kt = 0; kt < 8; kt++) {
        const int cur = kt & 1;
        if (kt < 7) {
            const int p0 = (kt + 1) * 8 + pr;
            wv = *(const uint4*)&Mb[p0 * 128 + r4];
            xv = *(const uint4*)&qb[(size_t)p0 * NN + r4];
        }
        slab_mma(f, sA + cur * SLAB_U32, sB + cur * SLAB_U32, mbase, nbase, gid, tig);
        if (kt < 7) {
            *(uint4*)&sA[(1 - cur) * SLAB_U32 + pr * PSTRIDE + r4] = wv;
            *(uint4*)&sB[(1 - cur) * SLAB_U32 + pr * PSTRIDE + r4] = xv;
            __syncthreads();
        }
    }

    float* outp = g_y + (size_t)b * C * NN + n0;
    float lsum = 0.f, lsq = 0.f;
#pragma unroll
    for (int mt = 0; mt < 4; mt++) {
        int row = mbase + mt * 16 + gid;
        float bb0 = bo[row], bb8 = bo[row + 8];
#pragma unroll
        for (int nt = 0; nt < 4; nt++) {
            int col = nbase + nt * 8 + tig * 2;
            float v0 = f.d[mt][nt][0] + bb0, v1 = f.d[mt][nt][1] + bb0;
            float v2 = f.d[mt][nt][2] + bb8, v3 = f.d[mt][nt][3] + bb8;
            *(float2*)&outp[(size_t)row * NN + col] = make_float2(v0, v1);
            *(float2*)&outp[(size_t)(row + 8) * NN + col] = make_float2(v2, v3);
            lsum += v0 + v1 + v2 + v3;
            lsq  += v0 * v0 + v1 * v1 + v2 * v2 + v3 * v3;
        }
    }
#pragma unroll
    for (int o = 16; o; o >>= 1) {
        lsum += __shfl_xor_sync(0xffffffffu, lsum, o);
        lsq  += __shfl_xor_sync(0xffffffffu, lsq,  o);
    }
    if (lane == 0) { redS[wid] = lsum; redQ[wid] = lsq; }
    __syncthreads();
    if (tid == 0) {
        float s = 0.f, q = 0.f;
#pragma unroll
        for (int i = 0; i < 8; i++) { s += redS[i]; q += redQ[i]; }
        atomicAdd(&g_sum[b], s);
        atomicAdd(&g_sumsq[b], q);
    }
}

// ---------------- K5: GroupNorm, float4 ----------------
__global__ void __launch_bounds__(256) k5_norm(
    const float* __restrict__ gn_w, const float* __restrict__ gn_b,
    float* __restrict__ out)
{
    int i4 = blockIdx.x * 256 + threadIdx.x;
    int b = i4 >> 17;
    int c = (i4 >> 10) & 127;
    const float cn = (float)(C * NN);
    float mu = g_sum[b] / cn;
    float var = g_sumsq[b] / cn - mu * mu;
    float is = rsqrtf(var + GEPS);
    float w = gn_w[c] * is, bb = gn_b[c] - mu * w;
    float4 v = *(const float4*)&g_y[(size_t)i4 * 4];
    v.x = v.x * w + bb; v.y = v.y * w + bb;
    v.z = v.z * w + bb; v.w = v.w * w + bb;
    *(float4*)&out[(size_t)i4 * 4] = v;
}

// ---------------- launch ----------------
extern "C" void kernel_launch(void* const* d_in, const int* in_sizes, int n_in,
                              void* d_out, int out_size)
{
    const float* x  = (const float*)d_in[0];
    const float* Wq = (const float*)d_in[1];
    const float* Wk = (const float*)d_in[2];
    const float* Wv = (const float*)d_in[3];
    const float* Wo = (const float*)d_in[4];
    const float* bo = (const float*)d_in[5];
    const float* gw = (const float*)d_in[6];
    const float* gb = (const float*)d_in[7];
    float* out = (float*)d_out;

    static int smem_set = 0;
    const int K1_SMEM = 128 * 132 * 4;   // 67584 B
    if (!smem_set) {
        cudaFuncSetAttribute(k1_fused, cudaFuncAttributeMaxDynamicSharedMemorySize, K1_SMEM);
        smem_set = 1;
    }

    k0_zero<<<132, 256>>>();
    k1_fused<<<dim3(32, 32), 256, K1_SMEM>>>(x, Wq, Wk, Wv);
    k2_ctx<<<dim3(8, 128), 256>>>();
    k3_fold<<<dim3(32, 32), 256>>>(Wo);
    k4_out<<<dim3(32, 32), 256>>>(bo);
    k5_norm<<<16384, 256>>>(gw, gb, out);
}

// round 11
// speedup vs baseline: 1.9084x; 1.0125x over previous
#include <cuda_runtime.h>
#include <cstdint>
#include <math.h>

#define B 32
#define C 128
#define NN 4096
#define HEADS 4
#define DH 32
#define HIDDEN 128
#define QSCALE 0.17677669529663687f   /* 32^-0.5 */
#define GEPS 1e-5f

// ---------------- scratch ----------------
__device__ uint32_t g_kv[(size_t)B * 2 * 128 * 2048];  // k/v packed bf16x2 [b][kv][row][npair]
__device__ uint32_t g_qbf[(size_t)B * 64 * NN];        // softmaxed q, bf16x2 [pair][n]
__device__ uint32_t g_Mbf[B * 64 * HIDDEN];            // folded M, bf16x2 [pair][row]
__device__ float g_ctx[B * HEADS * DH * DH];
__device__ float g_rsum[B * HIDDEN];
__device__ float g_y[(size_t)B * C * NN];
__device__ float g_sum[B];
__device__ float g_sumsq[B];

__device__ __forceinline__ uint32_t pack_bf16(float lo, float hi) {
    uint32_t r;
    asm("cvt.rn.bf16x2.f32 %0, %1, %2;" : "=r"(r) : "f"(hi), "f"(lo));
    return r;
}

__device__ __forceinline__ void mma_bf16(float* d, const uint32_t* a, const uint32_t* b) {
    asm("mma.sync.aligned.m16n8k16.row.col.f32.bf16.bf16.f32 "
        "{%0,%1,%2,%3}, {%4,%5,%6,%7}, {%8,%9}, {%0,%1,%2,%3};"
        : "+f"(d[0]), "+f"(d[1]), "+f"(d[2]), "+f"(d[3])
        : "r"(a[0]), "r"(a[1]), "r"(a[2]), "r"(a[3]), "r"(b[0]), "r"(b[1]));
}

// ---------------- K0: zero accumulators ----------------
__global__ void __launch_bounds__(256) k0_zero() {
    int gid = blockIdx.x * 256 + threadIdx.x;
    float4 z = make_float4(0.f, 0.f, 0.f, 0.f);
    if (gid < 32768) ((float4*)g_ctx)[gid] = z;
    if (gid < 1024)  ((float4*)g_rsum)[gid] = z;
    if (gid < 32) { g_sum[gid] = 0.f; g_sumsq[gid] = 0.f; }
}

// ---------------- bf16 mma helpers ----------------
#define PSTRIDE 136
#define SLAB_U32 (8 * PSTRIDE)

struct Frag { float d[4][4][4]; };

__device__ __forceinline__ void stage_A(
    uint32_t* sA, int arow, int ah, const float4& w0, const float4& w1)
{
    sA[(ah * 4 + 0) * PSTRIDE + arow] = pack_bf16(w0.x, w0.y);
    sA[(ah * 4 + 1) * PSTRIDE + arow] = pack_bf16(w0.z, w0.w);
    sA[(ah * 4 + 2) * PSTRIDE + arow] = pack_bf16(w1.x, w1.y);
    sA[(ah * 4 + 3) * PSTRIDE + arow] = pack_bf16(w1.z, w1.w);
}

__device__ __forceinline__ void slab_mma(
    Frag& f, const uint32_t* sA, const uint32_t* sB,
    int mbase, int nbase, int gid, int tig)
{
    uint32_t a[4][4], bf[4][2];
#pragma unroll
    for (int mt = 0; mt < 4; mt++) {
        int row = mbase + mt * 16 + gid;
        a[mt][0] = sA[tig * PSTRIDE + row];
        a[mt][1] = sA[tig * PSTRIDE + row + 8];
        a[mt][2] = sA[(tig + 4) * PSTRIDE + row];
        a[mt][3] = sA[(tig + 4) * PSTRIDE + row + 8];
    }
#pragma unroll
    for (int nt = 0; nt < 4; nt++) {
        int col = nbase + nt * 8 + gid;
        bf[nt][0] = sB[tig * PSTRIDE + col];
        bf[nt][1] = sB[(tig + 4) * PSTRIDE + col];
    }
#pragma unroll
    for (int mt = 0; mt < 4; mt++)
#pragma unroll
        for (int nt = 0; nt < 4; nt++)
            mma_bf16(f.d[mt][nt], a[mt], bf[nt]);
}

// stage full x tile (128 k x 128 n) as bf16 pairs into sX
__device__ __forceinline__ void stage_x_tile(
    uint32_t* sX, const float* __restrict__ xb, int tid)
{
    const int colg = (tid & 31) * 4;
    const int pr0 = tid >> 5;
#pragma unroll
    for (int i = 0; i < 8; i++) {
        int pair = i * 8 + pr0;
        float4 x0 = *(const float4*)&xb[(size_t)(2 * pair) * NN + colg];
        float4 x1 = *(const float4*)&xb[(size_t)(2 * pair + 1) * NN + colg];
        uint4 p;
        p.x = pack_bf16(x0.x, x1.x);
        p.y = pack_bf16(x0.y, x1.y);
        p.z = pack_bf16(x0.z, x1.z);
        p.w = pack_bf16(x0.w, x1.w);
        *(uint4*)&sX[pair * PSTRIDE + colg] = p;
    }
}

// W-vs-x mainloop, double-buffered W slabs
__device__ __forceinline__ void gemm_Wx(
    Frag& f, uint32_t* sA, const uint32_t* sX, const float* __restrict__ Wp,
    int tid, int mbase, int nbase, int gid, int tig)
{
    const int arow = tid & 127, ah = tid >> 7;
#pragma unroll
    for (int mt = 0; mt < 4; mt++)
#pragma unroll
        for (int nt = 0; nt < 4; nt++)
#pragma unroll
            for (int r = 0; r < 4; r++) f.d[mt][nt][r] = 0.f;

    float4 w0 = *(const float4*)&Wp[arow * 128 + ah * 8];
    float4 w1 = *(const float4*)&Wp[arow * 128 + ah * 8 + 4];
    stage_A(sA, arow, ah, w0, w1);
    __syncthreads();

    for (int kt = 0; kt < 8; kt++) {
        const int cur = kt & 1;
        if (kt < 7) {
            const int k0 = (kt + 1) * 16;
            w0 = *(const float4*)&Wp[arow * 128 + k0 + ah * 8];
            w1 = *(const float4*)&Wp[arow * 128 + k0 + ah * 8 + 4];
        }
        slab_mma(f, sA + cur * SLAB_U32, sX + kt * SLAB_U32, mbase, nbase, gid, tig);
        if (kt < 7) {
            stage_A(sA + (1 - cur) * SLAB_U32, arow, ah, w0, w1);
            __syncthreads();
        }
    }
}

// ---------------- K1a: k,v projections ----------------
// grid (32 ncol, 32 b), 256 threads
__global__ void __launch_bounds__(256) k1_kv(
    const float* __restrict__ x,
    const float* __restrict__ Wk,
    const float* __restrict__ Wv)
{
    extern __shared__ uint32_t dsm[];
    uint32_t* sA = dsm;
    uint32_t* sX = dsm + 2 * SLAB_U32;

    const int b  = blockIdx.y;
    const int n0 = blockIdx.x * 128;
    const int tid = threadIdx.x;
    const int lane = tid & 31, wid = tid >> 5;
    const int mbase = (wid >> 2) * 64, nbase = (wid & 3) * 32;
    const int gid = lane >> 2, tig = lane & 3;

    stage_x_tile(sX, x + (size_t)b * C * NN + n0, tid);
    __syncthreads();

#pragma unroll 1
    for (int kv = 0; kv < 2; kv++) {
        const float* Wp = (kv == 0) ? Wk : Wv;
        Frag f;
        gemm_Wx(f, sA, sX, Wp, tid, mbase, nbase, gid, tig);

        uint32_t* outp = g_kv + ((size_t)(b * 2 + kv) * 128) * 2048 + (n0 >> 1);
#pragma unroll
        for (int mt = 0; mt < 4; mt++) {
#pragma unroll
            for (int nt = 0; nt < 4; nt++) {
                int row = mbase + mt * 16 + gid;
                int npair = ((nbase + nt * 8) >> 1) + tig;
                outp[(size_t)row * 2048 + npair] =
                    pack_bf16(f.d[mt][nt][0], f.d[mt][nt][1]);
                outp[(size_t)(row + 8) * 2048 + npair] =
                    pack_bf16(f.d[mt][nt][2], f.d[mt][nt][3]);
            }
        }
        __syncthreads();
    }
}

// ---------------- K1b: q projection + softmax, packed bf16 out ----------------
// grid (32 ncol, 32 b), 256 threads
__global__ void __launch_bounds__(256) k1_q(
    const float* __restrict__ x,
    const float* __restrict__ Wq)
{
    extern __shared__ uint32_t dsm[];
    uint32_t* sA = dsm;
    uint32_t* sX = dsm + 2 * SLAB_U32;
    float* stage = (float*)dsm;   // aliased [128][132] epilogue

    const int b  = blockIdx.y;
    const int n0 = blockIdx.x * 128;
    const int tid = threadIdx.x;
    const int lane = tid & 31, wid = tid >> 5;
    const int mbase = (wid >> 2) * 64, nbase = (wid & 3) * 32;
    const int gid = lane >> 2, tig = lane & 3;

    stage_x_tile(sX, x + (size_t)b * C * NN + n0, tid);
    __syncthreads();

    Frag f;
    gemm_Wx(f, sA, sX, Wq, tid, mbase, nbase, gid, tig);

    __syncthreads();
#pragma unroll
    for (int mt = 0; mt < 4; mt++) {
#pragma unroll
        for (int nt = 0; nt < 4; nt++) {
            int row = mbase + mt * 16 + gid;
            int col = nbase + nt * 8 + tig * 2;
            *(float2*)&stage[row * 132 + col] =
                make_float2(f.d[mt][nt][0], f.d[mt][nt][1]);
            *(float2*)&stage[(row + 8) * 132 + col] =
                make_float2(f.d[mt][nt][2], f.d[mt][nt][3]);
        }
    }
    __syncthreads();

    uint32_t* outq = g_qbf + (size_t)b * 64 * NN + n0;
#pragma unroll
    for (int t = tid; t < 512; t += 256) {
        const int col = t & 127;
        const int h = t >> 7;
        float sum = 0.f;
#pragma unroll
        for (int dd = 0; dd < 32; dd++) {
            float* p = &stage[(h * 32 + dd) * 132 + col];
            float e = __expf(*p);
            *p = e;
            sum += e;
        }
        float inv = QSCALE / sum;
#pragma unroll
        for (int dp = 0; dp < 16; dp++) {
            float lo = stage[(h * 32 + 2 * dp) * 132 + col] * inv;
            float hi = stage[(h * 32 + 2 * dp + 1) * 132 + col] * inv;
            outq[(size_t)(h * 16 + dp) * NN + col] = pack_bf16(lo, hi);
        }
    }
}

// ---------------- K2: bf16 mma partial ctx = exp(k) @ v^T + rowsum ----------------
#define K2PAD 34
#define K2HALF (128 * K2PAD)
__global__ void __launch_bounds__(256) k2_ctx()
{
    __shared__ uint32_t s2[2 * K2HALF];
    uint32_t* sKb = s2;
    uint32_t* sVb = s2 + K2HALF;

    const int bh = blockIdx.y;
    const int b = bh >> 2, h = bh & 3;
    const int cbp = blockIdx.x * 256;
    const uint32_t* kb32 = g_kv + ((size_t)(b * 2 + 0) * 128 + h * 32) * 2048 + cbp;
    const uint32_t* vb32 = g_kv + ((size_t)(b * 2 + 1) * 128 + h * 32) * 2048 + cbp;

    const int tid = threadIdx.x;
    const int lane = tid & 31, w = tid >> 5;
    const int gid = lane >> 2, tig = lane & 3;

    const int row = tid >> 3;
    const int t   = tid & 7;

    float c[2][4][4];
#pragma unroll
    for (int mt = 0; mt < 2; mt++)
#pragma unroll
        for (int nt = 0; nt < 4; nt++)
#pragma unroll
            for (int r = 0; r < 4; r++) c[mt][nt][r] = 0.f;
    float lsum = 0.f;

#pragma unroll 1
    for (int half = 0; half < 2; half++) {
        const int pb = half * 128;
        __syncthreads();
#pragma unroll
        for (int j = 0; j < 8; j++) {
            int pr = 2 * t + 16 * j;
            uint2 kk = *(const uint2*)&kb32[(size_t)row * 2048 + pb + pr];
            float a0 = __uint_as_float(kk.x << 16);
            float a1 = __uint_as_float(kk.x & 0xffff0000u);
            float a2 = __uint_as_float(kk.y << 16);
            float a3 = __uint_as_float(kk.y & 0xffff0000u);
            float e0 = __expf(a0), e1 = __expf(a1);
            float e2 = __expf(a2), e3 = __expf(a3);
            lsum += e0 + e1 + e2 + e3;
            sKb[pr * K2PAD + row] = pack_bf16(e0, e1);
            sKb[(pr + 1) * K2PAD + row] = pack_bf16(e2, e3);
            uint2 vv = *(const uint2*)&vb32[(size_t)row * 2048 + pb + pr];
            sVb[pr * K2PAD + row] = vv.x;
            sVb[(pr + 1) * K2PAD + row] = vv.y;
        }
        __syncthreads();
#pragma unroll
        for (int kt = 0; kt < 2; kt++) {
            const int base = w * 16 + kt * 8;
            uint32_t a[2][4], bf[4][2];
#pragma unroll
            for (int mt = 0; mt < 2; mt++) {
                int r2 = mt * 16 + gid;
                a[mt][0] = sKb[(base + tig) * K2PAD + r2];
                a[mt][1] = sKb[(base + tig) * K2PAD + r2 + 8];
                a[mt][2] = sKb[(base + tig + 4) * K2PAD + r2];
                a[mt][3] = sKb[(base + tig + 4) * K2PAD + r2 + 8];
            }
#pragma unroll
            for (int nt = 0; nt < 4; nt++) {
                int col = nt * 8 + gid;
                bf[nt][0] = sVb[(base + tig) * K2PAD + col];
                bf[nt][1] = sVb[(base + tig + 4) * K2PAD + col];
            }
#pragma unroll
            for (int mt = 0; mt < 2; mt++)
#pragma unroll
                for (int nt = 0; nt < 4; nt++)
                    mma_bf16(c[mt][nt], a[mt], bf[nt]);
        }
    }

#pragma unroll
    for (int o = 4; o; o >>= 1) lsum += __shfl_xor_sync(0xffffffffu, lsum, o);
    if ((tid & 7) == 0)
        atomicAdd(&g_rsum[b * HIDDEN + h * 32 + row], lsum);

    __syncthreads();
    float* pbuf = (float*)s2;
#pragma unroll
    for (int mt = 0; mt < 2; mt++) {
#pragma unroll
        for (int nt = 0; nt < 4; nt++) {
            int r2 = mt * 16 + gid;
            int col = nt * 8 + tig * 2;
            pbuf[(w * 32 + r2) * K2PAD + col]     = c[mt][nt][0];
            pbuf[(w * 32 + r2) * K2PAD + col + 1] = c[mt][nt][1];
            pbuf[(w * 32 + r2 + 8) * K2PAD + col]     = c[mt][nt][2];
            pbuf[(w * 32 + r2 + 8) * K2PAD + col + 1] = c[mt][nt][3];
        }
    }
    __syncthreads();
    {
        const int d = tid >> 3;
        const int e0 = (tid & 7) * 4;
        float s0 = 0.f, s1 = 0.f, s2v = 0.f, s3 = 0.f;
#pragma unroll
        for (int ww = 0; ww < 8; ww++) {
            const float* p = &pbuf[(ww * 32 + d) * K2PAD + e0];
            s0 += p[0]; s1 += p[1]; s2v += p[2]; s3 += p[3];
        }
        float* cp = &g_ctx[((size_t)bh * 32 + d) * 32 + e0];
        atomicAdd(cp + 0, s0);
        atomicAdd(cp + 1, s1);
        atomicAdd(cp + 2, s2v);
        atomicAdd(cp + 3, s3);
    }
}

// ---------------- K3: M_b = Wo @ blockdiag(ctx^T / rsum), packed bf16 out ----------------
__global__ void __launch_bounds__(256) k3_fold(const float* __restrict__ Wo)
{
    const int b = blockIdx.y;
    const int og = blockIdx.x * 4;
    __shared__ float sctx[HEADS * DH * DH];
    __shared__ float sinv[HIDDEN];
    const int tid = threadIdx.x;
#pragma unroll
    for (int rr = 0; rr < 4; rr++) {
        int idx = tid + rr * 256;
        *(float4*)&sctx[idx * 4] = *(const float4*)&g_ctx[(size_t)b * 4096 + idx * 4];
    }
    if (tid < 128) sinv[tid] = 1.0f / g_rsum[b * HIDDEN + tid];
    __syncthreads();

    const int o = og + (tid >> 6);
    const int col0 = (tid & 63) * 2;
    const int h = col0 >> 5;
    const int d0 = col0 & 31;

    float wo[32];
#pragma unroll
    for (int q4 = 0; q4 < 8; q4++) {
        float4 t = *(const float4*)&Wo[o * 128 + h * 32 + q4 * 4];
        wo[q4 * 4 + 0] = t.x; wo[q4 * 4 + 1] = t.y;
        wo[q4 * 4 + 2] = t.z; wo[q4 * 4 + 3] = t.w;
    }
    float4 a0 = make_float4(0.f, 0.f, 0.f, 0.f);
    float4 a1 = make_float4(0.f, 0.f, 0.f, 0.f);
#pragma unroll
    for (int q4 = 0; q4 < 8; q4++) {
        float4 c0v = *(const float4*)&sctx[(h * 32 + d0) * 32 + q4 * 4];
        float4 c1v = *(const float4*)&sctx[(h * 32 + d0 + 1) * 32 + q4 * 4];
        a0.x += wo[q4 * 4 + 0] * c0v.x; a0.y += wo[q4 * 4 + 1] * c0v.y;
        a0.z += wo[q4 * 4 + 2] * c0v.z; a0.w += wo[q4 * 4 + 3] * c0v.w;
        a1.x += wo[q4 * 4 + 0] * c1v.x; a1.y += wo[q4 * 4 + 1] * c1v.y;
        a1.z += wo[q4 * 4 + 2] * c1v.z; a1.w += wo[q4 * 4 + 3] * c1v.w;
    }
    float s0 = (a0.x + a0.y) + (a0.z + a0.w);
    float s1 = (a1.x + a1.y) + (a1.z + a1.w);
    g_Mbf[b * 8192 + (col0 >> 1) * 128 + o] =
        pack_bf16(s0 * sinv[col0], s1 * sinv[col0 + 1]);
}

// ---------------- K4: bf16 mma y = M_b @ softq + bo, + stats ----------------
__global__ void __launch_bounds__(256) k4_out(const float* __restrict__ bo)
{
    __shared__ uint32_t sA[2 * SLAB_U32];
    __shared__ uint32_t sB[2 * SLAB_U32];
    __shared__ float redS[8], redQ[8];

    const int b  = blockIdx.y;
    const int n0 = blockIdx.x * 128;
    const int tid = threadIdx.x;
    const int lane = tid & 31, wid = tid >> 5;
    const int mbase = (wid >> 2) * 64, nbase = (wid & 3) * 32;
    const int gid = lane >> 2, tig = lane & 3;

    const uint32_t* Mb = g_Mbf + b * 8192;
    const uint32_t* qb = g_qbf + (size_t)b * 64 * NN + n0;

    const int pr = tid >> 5;
    const int r4 = (tid & 31) * 4;

    Frag f;
#pragma unroll
    for (int mt = 0; mt < 4; mt++)
#pragma unroll
        for (int nt = 0; nt < 4; nt++)
#pragma unroll
            for (int r = 0; r < 4; r++) f.d[mt][nt][r] = 0.f;

    uint4 wv = *(const uint4*)&Mb[pr * 128 + r4];
    uint4 xv = *(const uint4*)&qb[(size_t)pr * NN + r4];
    *(uint4*)&sA[pr * PSTRIDE + r4] = wv;
    *(uint4*)&sB[pr * PSTRIDE + r4] = xv;
    __syncthreads();

    for (int kt = 0; kt < 8; kt++) {
        const int cur = kt & 1;
        if (kt < 7) {
            const int p0 = (kt + 1) * 8 + pr;
            wv = *(const uint4*)&Mb[p0 * 128 + r4];
            xv = *(const uint4*)&qb[(size_t)p0 * NN + r4];
        }
        slab_mma(f, sA + cur * SLAB_U32, sB + cur * SLAB_U32, mbase, nbase, gid, tig);
        if (kt < 7) {
            *(uint4*)&sA[(1 - cur) * SLAB_U32 + pr * PSTRIDE + r4] = wv;
            *(uint4*)&sB[(1 - cur) * SLAB_U32 + pr * PSTRIDE + r4] = xv;
            __syncthreads();
        }
    }

    float* outp = g_y + (size_t)b * C * NN + n0;
    float lsum = 0.f, lsq = 0.f;
#pragma unroll
    for (int mt = 0; mt < 4; mt++) {
        int row = mbase + mt * 16 + gid;
        float bb0 = bo[row], bb8 = bo[row + 8];
#pragma unroll
        for (int nt = 0; nt < 4; nt++) {
            int col = nbase + nt * 8 + tig * 2;
            float v0 = f.d[mt][nt][0] + bb0, v1 = f.d[mt][nt][1] + bb0;
            float v2 = f.d[mt][nt][2] + bb8, v3 = f.d[mt][nt][3] + bb8;
            *(float2*)&outp[(size_t)row * NN + col] = make_float2(v0, v1);
            *(float2*)&outp[(size_t)(row + 8) * NN + col] = make_float2(v2, v3);
            lsum += v0 + v1 + v2 + v3;
            lsq  += v0 * v0 + v1 * v1 + v2 * v2 + v3 * v3;
        }
    }
#pragma unroll
    for (int o = 16; o; o >>= 1) {
        lsum += __shfl_xor_sync(0xffffffffu, lsum, o);
        lsq  += __shfl_xor_sync(0xffffffffu, lsq,  o);
    }
    if (lane == 0) { redS[wid] = lsum; redQ[wid] = lsq; }
    __syncthreads();
    if (tid == 0) {
        float s = 0.f, q = 0.f;
#pragma unroll
        for (int i = 0; i < 8; i++) { s += redS[i]; q += redQ[i]; }
        atomicAdd(&g_sum[b], s);
        atomicAdd(&g_sumsq[b], q);
    }
}

// ---------------- K5: GroupNorm, float4 ----------------
__global__ void __launch_bounds__(256) k5_norm(
    const float* __restrict__ gn_w, const float* __restrict__ gn_b,
    float* __restrict__ out)
{
    int i4 = blockIdx.x * 256 + threadIdx.x;
    int b = i4 >> 17;
    int c = (i4 >> 10) & 127;
    const float cn = (float)(C * NN);
    float mu = g_sum[b] / cn;
    float var = g_sumsq[b] / cn - mu * mu;
    float is = rsqrtf(var + GEPS);
    float w = gn_w[c] * is, bb = gn_b[c] - mu * w;
    float4 v = *(const float4*)&g_y[(size_t)i4 * 4];
    v.x = v.x * w + bb; v.y = v.y * w + bb;
    v.z = v.z * w + bb; v.w = v.w * w + bb;
    *(float4*)&out[(size_t)i4 * 4] = v;
}

// ---------------- launch (fork-join: k2,k3 overlap k1_q) ----------------
extern "C" void kernel_launch(void* const* d_in, const int* in_sizes, int n_in,
                              void* d_out, int out_size)
{
    const float* x  = (const float*)d_in[0];
    const float* Wq = (const float*)d_in[1];
    const float* Wk = (const float*)d_in[2];
    const float* Wv = (const float*)d_in[3];
    const float* Wo = (const float*)d_in[4];
    const float* bo = (const float*)d_in[5];
    const float* gw = (const float*)d_in[6];
    const float* gb = (const float*)d_in[7];
    float* out = (float*)d_out;

    static int inited = 0;
    static cudaStream_t s2;
    static cudaEvent_t ev1, ev2;
    const int KV_SMEM = (2 * SLAB_U32 + 64 * PSTRIDE) * 4;   // 43520 B
    const int Q_SMEM  = 128 * 132 * 4;                       // 67584 B (epilogue alias)
    if (!inited) {
        cudaFuncSetAttribute(k1_kv, cudaFuncAttributeMaxDynamicSharedMemorySize, KV_SMEM);
        cudaFuncSetAttribute(k1_q,  cudaFuncAttributeMaxDynamicSharedMemorySize, Q_SMEM);
        cudaStreamCreateWithFlags(&s2, cudaStreamNonBlocking);
        cudaEventCreateWithFlags(&ev1, cudaEventDisableTiming);
        cudaEventCreateWithFlags(&ev2, cudaEventDisableTiming);
        inited = 1;
    }

    k0_zero<<<132, 256>>>();
    k1_kv<<<dim3(32, 32), 256, KV_SMEM>>>(x, Wk, Wv);
    cudaEventRecord(ev1, 0);

    // side stream: k2 -> k3 (needs only k/v + zeroed accumulators)
    cudaStreamWaitEvent(s2, ev1, 0);
    k2_ctx<<<dim3(8, 128), 256, 0, s2>>>();
    k3_fold<<<dim3(32, 32), 256, 0, s2>>>(Wo);
    cudaEventRecord(ev2, s2);

    // main stream: q projection concurrently
    k1_q<<<dim3(32, 32), 256, Q_SMEM>>>(x, Wq);

    cudaStreamWaitEvent(0, ev2, 0);
    k4_out<<<dim3(32, 32), 256>>>(bo);
    k5_norm<<<16384, 256>>>(gw, gb, out);
}